// round 1
// baseline (speedup 1.0000x reference)
#include <cuda_runtime.h>
#include <cstdint>

// ---------------------------------------------------------------------------
// Scratch buffers (device globals; no allocation allowed)
// ---------------------------------------------------------------------------
__device__ float g_w1 [786432];    // [4,12,128,128]
__device__ float g_c1 [1048576];   // [4,16,128,128]
__device__ float g_w2 [1048576];   // [4,64,64,64]
__device__ float g_c2 [1048576];   // [4,64,64,64]
__device__ float g_w3 [1048576];   // [4,256,32,32]
__device__ float g_c3 [1048576];   // [4,256,32,32]
__device__ float g_w4 [1048576];   // [4,1024,16,16]
__device__ float g_c4 [1048576];
__device__ float g_c5 [1048576];
__device__ float g_ic4[1048576];
__device__ float g_iw4[2097152];   // [4,512,32,32]
__device__ float g_ic3[1048576];   // [4,256,32,32]
__device__ float g_iw3[2097152];   // [4,128,64,64]
__device__ float g_ic2[1048576];   // [4,64,64,64]
__device__ float g_iw2[2097152];   // [4,32,128,128]
__device__ float g_ic1[1048576];   // [4,16,128,128]
__device__ float g_iw1[786432];    // [4,12,128,128]

// ---------------------------------------------------------------------------
// Haar DWT: in[B,C,H,W] -> out[B,4C,H/2,W/2], channel = 4*c + band
// bands 1..3 get the (v+1)/2 affine.
// ---------------------------------------------------------------------------
__global__ void wt_k(const float* __restrict__ in, float* __restrict__ out,
                     int B, int C, int H, int W) {
    int Ho = H >> 1, Wo = W >> 1;
    int total = B * C * Ho * Wo;
    int i = blockIdx.x * blockDim.x + threadIdx.x;
    if (i >= total) return;
    int w = i % Wo;
    int h = (i / Wo) % Ho;
    int c = (i / (Wo * Ho)) % C;
    int b = i / (Wo * Ho * C);
    const float* p = in + ((size_t)(b * C + c) * H + 2 * h) * W + 2 * w;
    float a  = p[0], bb = p[1], cc = p[W], d = p[W + 1];
    float ll = 0.25f * (a + bb + cc + d);
    float hl = 0.5f  * (a + bb - cc - d);
    float lh = 0.5f  * (a - bb + cc - d);
    float hh = 0.5f  * (a - bb - cc + d);
    size_t ob = ((size_t)(b * 4 * C + 4 * c) * Ho + h) * Wo + w;
    size_t cs = (size_t)Ho * Wo;
    out[ob]          = ll;
    out[ob + cs]     = (hl + 1.f) * 0.5f;
    out[ob + 2 * cs] = (lh + 1.f) * 0.5f;
    out[ob + 3 * cs] = (hh + 1.f) * 0.5f;
}

// ---------------------------------------------------------------------------
// Haar IWT: in[B,C4,H,W] -> out[b, coff + c, 2H, 2W] inside a Ctot-channel buf
// high bands get 2v-1 first.
// ---------------------------------------------------------------------------
__global__ void iwt_k(const float* __restrict__ in, float* __restrict__ out,
                      int B, int C4, int H, int W, int Ctot, int coff) {
    int C = C4 >> 2;
    int total = B * C * H * W;
    int i = blockIdx.x * blockDim.x + threadIdx.x;
    if (i >= total) return;
    int w = i % W;
    int h = (i / W) % H;
    int c = (i / (W * H)) % C;
    int b = i / (W * H * C);
    size_t ib = ((size_t)(b * C4 + 4 * c) * H + h) * W + w;
    size_t cs = (size_t)H * W;
    float v0 = in[ib];
    float v1 = 2.f * in[ib + cs]     - 1.f;
    float v2 = 2.f * in[ib + 2 * cs] - 1.f;
    float v3 = 2.f * in[ib + 3 * cs] - 1.f;
    float x00 = v0 + 0.5f * ( v1 + v2 + v3);
    float x01 = v0 + 0.5f * ( v1 - v2 - v3);
    float x10 = v0 + 0.5f * (-v1 + v2 - v3);
    float x11 = v0 + 0.5f * (-v1 - v2 + v3);
    int W2 = 2 * W;
    size_t ob = ((size_t)(b * Ctot + coff + c) * 2 * H + 2 * h) * W2 + 2 * w;
    out[ob]          = x00;
    out[ob + 1]      = x01;
    out[ob + W2]     = x10;
    out[ob + W2 + 1] = x11;
}

// ---------------------------------------------------------------------------
// copy skip connection into the front channels of a concat buffer
// ---------------------------------------------------------------------------
__global__ void copyskip_k(const float* __restrict__ src, float* __restrict__ dst,
                           int B, int Csrc, int Ctot, int HW) {
    int total = B * Csrc * HW;
    int i = blockIdx.x * blockDim.x + threadIdx.x;
    if (i >= total) return;
    int p = i % HW;
    int c = (i / HW) % Csrc;
    int b = i / (HW * Csrc);
    dst[((size_t)(b * Ctot) + c) * HW + p] = src[((size_t)(b * Csrc) + c) * HW + p];
}

// ---------------------------------------------------------------------------
// Direct 3x3 conv, pad=1, stride=1.
// Each thread: 2x2 output pixels x OCB output channels.
// Block tile: TH x TW spatial, (TH/2)*(TW/2) threads. H%TH==0, W%TW==0.
// ---------------------------------------------------------------------------
template <int TH, int TW, int OCB, bool RELU, bool ADD>
__global__ void conv3x3_k(const float* __restrict__ in, const float* __restrict__ wgt,
                          const float* __restrict__ bias, const float* __restrict__ addsrc,
                          float* __restrict__ out, int IC, int OC, int H, int W) {
    constexpr int NT = (TH / 2) * (TW / 2);
    __shared__ float s_in[(TH + 2) * (TW + 2)];
    __shared__ float s_w[OCB * 9];

    const int tiles_h = H / TH;
    const int tile_w  = blockIdx.x;
    const int tile_h  = blockIdx.y % tiles_h;
    const int b       = blockIdx.y / tiles_h;
    const int oc0     = blockIdx.z * OCB;
    const int tid     = threadIdx.x;
    const int tx      = tid % (TW / 2);
    const int ty      = tid / (TW / 2);
    const int w0      = tile_w * TW + 2 * tx;
    const int h0      = tile_h * TH + 2 * ty;

    float acc[OCB][4];
#pragma unroll
    for (int o = 0; o < OCB; o++) {
        float bv = bias[oc0 + o];
        acc[o][0] = bv; acc[o][1] = bv; acc[o][2] = bv; acc[o][3] = bv;
    }

    const float* inb = in + (size_t)b * IC * H * W;
    for (int ic = 0; ic < IC; ic++) {
        const float* inc = inb + (size_t)ic * H * W;
        // input tile with 1-halo (zero padded)
        for (int i = tid; i < (TH + 2) * (TW + 2); i += NT) {
            int r  = i / (TW + 2);
            int cq = i % (TW + 2);
            int gh = tile_h * TH - 1 + r;
            int gw = tile_w * TW - 1 + cq;
            float v = 0.f;
            if ((unsigned)gh < (unsigned)H && (unsigned)gw < (unsigned)W)
                v = inc[(size_t)gh * W + gw];
            s_in[i] = v;
        }
        // weights for OCB output channels at this ic
        for (int i = tid; i < OCB * 9; i += NT)
            s_w[i] = wgt[((size_t)(oc0 + i / 9) * IC + ic) * 9 + (i % 9)];
        __syncthreads();

        float r[4][4];
#pragma unroll
        for (int di = 0; di < 4; di++)
#pragma unroll
            for (int dj = 0; dj < 4; dj++)
                r[di][dj] = s_in[(2 * ty + di) * (TW + 2) + 2 * tx + dj];

#pragma unroll
        for (int o = 0; o < OCB; o++) {
            float w9[9];
#pragma unroll
            for (int j = 0; j < 9; j++) w9[j] = s_w[o * 9 + j];
#pragma unroll
            for (int pi = 0; pi < 2; pi++)
#pragma unroll
                for (int pj = 0; pj < 2; pj++) {
                    float s = acc[o][pi * 2 + pj];
#pragma unroll
                    for (int ki = 0; ki < 3; ki++)
#pragma unroll
                        for (int kj = 0; kj < 3; kj++)
                            s = fmaf(r[pi + ki][pj + kj], w9[ki * 3 + kj], s);
                    acc[o][pi * 2 + pj] = s;
                }
        }
        __syncthreads();
    }

#pragma unroll
    for (int o = 0; o < OCB; o++) {
        size_t base = ((size_t)(b * OC + oc0 + o) * H + h0) * W + w0;
#pragma unroll
        for (int pi = 0; pi < 2; pi++)
#pragma unroll
            for (int pj = 0; pj < 2; pj++) {
                float v = acc[o][pi * 2 + pj];
                if (ADD)  v += addsrc[base + (size_t)pi * W + pj];
                if (RELU) v = (v >= 0.f) ? v : 0.2f * v;
                out[base + (size_t)pi * W + pj] = v;
            }
    }
}

// ---------------------------------------------------------------------------
// Final: y = iwt(iw1[4,12,128,128]) -> [4,3,256,256]; out = cfin(3x3 1x1) @ y
// ---------------------------------------------------------------------------
__global__ void final_k(const float* __restrict__ in, const float* __restrict__ cfin,
                        float* __restrict__ out, int B) {
    const int H = 128, W = 128;
    int total = B * H * W;
    int i = blockIdx.x * blockDim.x + threadIdx.x;
    if (i >= total) return;
    int w = i % W;
    int h = (i / W) % H;
    int b = i / (W * H);

    float y00[3], y01[3], y10[3], y11[3];
#pragma unroll
    for (int c = 0; c < 3; c++) {
        size_t ib = ((size_t)(b * 12 + 4 * c) * H + h) * W + w;
        size_t cs = (size_t)H * W;
        float v0 = in[ib];
        float v1 = 2.f * in[ib + cs]     - 1.f;
        float v2 = 2.f * in[ib + 2 * cs] - 1.f;
        float v3 = 2.f * in[ib + 3 * cs] - 1.f;
        y00[c] = v0 + 0.5f * ( v1 + v2 + v3);
        y01[c] = v0 + 0.5f * ( v1 - v2 - v3);
        y10[c] = v0 + 0.5f * (-v1 + v2 - v3);
        y11[c] = v0 + 0.5f * (-v1 - v2 + v3);
    }
    float m[9];
#pragma unroll
    for (int j = 0; j < 9; j++) m[j] = cfin[j];  // cfin[o*3+c]

    const int HO = 256, WO = 256;
#pragma unroll
    for (int o = 0; o < 3; o++) {
        float o00 = m[o*3+0]*y00[0] + m[o*3+1]*y00[1] + m[o*3+2]*y00[2];
        float o01 = m[o*3+0]*y01[0] + m[o*3+1]*y01[1] + m[o*3+2]*y01[2];
        float o10 = m[o*3+0]*y10[0] + m[o*3+1]*y10[1] + m[o*3+2]*y10[2];
        float o11 = m[o*3+0]*y11[0] + m[o*3+1]*y11[1] + m[o*3+2]*y11[2];
        size_t ob = ((size_t)(b * 3 + o) * HO + 2 * h) * WO + 2 * w;
        out[ob]          = o00;
        out[ob + 1]      = o01;
        out[ob + WO]     = o10;
        out[ob + WO + 1] = o11;
    }
}

// ---------------------------------------------------------------------------
// Host side
// ---------------------------------------------------------------------------
static inline int ceil_div(int a, int b) { return (a + b - 1) / b; }

extern "C" void kernel_launch(void* const* d_in, const int* in_sizes, int n_in,
                              void* d_out, int out_size) {
    (void)in_sizes; (void)n_in; (void)out_size;
    const float* x        = (const float*)d_in[0];
    const float* conv1_w  = (const float*)d_in[1];
    const float* conv1_b  = (const float*)d_in[2];
    const float* conv2_w  = (const float*)d_in[3];
    const float* conv2_b  = (const float*)d_in[4];
    const float* conv3_w  = (const float*)d_in[5];
    const float* conv3_b  = (const float*)d_in[6];
    const float* conv4_w  = (const float*)d_in[7];
    const float* conv4_b  = (const float*)d_in[8];
    const float* convd4_w = (const float*)d_in[9];
    const float* convd4_b = (const float*)d_in[10];
    const float* convd3_w = (const float*)d_in[11];
    const float* convd3_b = (const float*)d_in[12];
    const float* convd2_w = (const float*)d_in[13];
    const float* convd2_b = (const float*)d_in[14];
    const float* convd1_w = (const float*)d_in[15];
    const float* convd1_b = (const float*)d_in[16];
    const float* cfin_w   = (const float*)d_in[17];
    float* out = (float*)d_out;

    static float *p_w1=nullptr,*p_c1,*p_w2,*p_c2,*p_w3,*p_c3,*p_w4,*p_c4,*p_c5,
                 *p_ic4,*p_iw4,*p_ic3,*p_iw3,*p_ic2,*p_iw2,*p_ic1,*p_iw1;
    if (!p_w1) {
        cudaGetSymbolAddress((void**)&p_w1,  g_w1);
        cudaGetSymbolAddress((void**)&p_c1,  g_c1);
        cudaGetSymbolAddress((void**)&p_w2,  g_w2);
        cudaGetSymbolAddress((void**)&p_c2,  g_c2);
        cudaGetSymbolAddress((void**)&p_w3,  g_w3);
        cudaGetSymbolAddress((void**)&p_c3,  g_c3);
        cudaGetSymbolAddress((void**)&p_w4,  g_w4);
        cudaGetSymbolAddress((void**)&p_c4,  g_c4);
        cudaGetSymbolAddress((void**)&p_c5,  g_c5);
        cudaGetSymbolAddress((void**)&p_ic4, g_ic4);
        cudaGetSymbolAddress((void**)&p_iw4, g_iw4);
        cudaGetSymbolAddress((void**)&p_ic3, g_ic3);
        cudaGetSymbolAddress((void**)&p_iw3, g_iw3);
        cudaGetSymbolAddress((void**)&p_ic2, g_ic2);
        cudaGetSymbolAddress((void**)&p_iw2, g_iw2);
        cudaGetSymbolAddress((void**)&p_ic1, g_ic1);
        cudaGetSymbolAddress((void**)&p_iw1, g_iw1);
    }

    const int B = 4;

    // --- encoder ---
    // w1 = wt(x): [4,3,256,256] -> [4,12,128,128]
    wt_k<<<ceil_div(B*3*128*128, 256), 256>>>(x, p_w1, B, 3, 256, 256);
    // c1 = lrelu(conv1(w1)) : 12->16 @128
    conv3x3_k<16,32,16,true,false><<<dim3(4, 8*B, 1), 128>>>(
        p_w1, conv1_w, conv1_b, nullptr, p_c1, 12, 16, 128, 128);
    // w2 = wt(c1): [4,64,64,64]
    wt_k<<<ceil_div(B*16*64*64, 256), 256>>>(p_c1, p_w2, B, 16, 128, 128);
    // c2 = lrelu(conv2(w2)) : 64->64 @64
    conv3x3_k<16,32,16,true,false><<<dim3(2, 4*B, 4), 128>>>(
        p_w2, conv2_w, conv2_b, nullptr, p_c2, 64, 64, 64, 64);
    // w3 = wt(c2): [4,256,32,32]
    wt_k<<<ceil_div(B*64*32*32, 256), 256>>>(p_c2, p_w3, B, 64, 64, 64);
    // c3 = lrelu(conv3(w3)) : 256->256 @32
    conv3x3_k<16,32,8,true,false><<<dim3(1, 2*B, 32), 128>>>(
        p_w3, conv3_w, conv3_b, nullptr, p_c3, 256, 256, 32, 32);
    // w4 = wt(c3): [4,1024,16,16]
    wt_k<<<ceil_div(B*256*16*16, 256), 256>>>(p_c3, p_w4, B, 256, 32, 32);

    // --- bottleneck: three conv4 ---
    conv3x3_k<16,16,8,true,false><<<dim3(1, 1*B, 128), 64>>>(
        p_w4, conv4_w, conv4_b, nullptr, p_c4, 1024, 1024, 16, 16);
    conv3x3_k<16,16,8,true,false><<<dim3(1, 1*B, 128), 64>>>(
        p_c4, conv4_w, conv4_b, nullptr, p_c5, 1024, 1024, 16, 16);
    // ic4 = lrelu(conv4(c5) + w4)
    conv3x3_k<16,16,8,true,true><<<dim3(1, 1*B, 128), 64>>>(
        p_c5, conv4_w, conv4_b, p_w4, p_ic4, 1024, 1024, 16, 16);

    // --- decoder ---
    // iw4 = concat([c3, iwt(ic4)]) : [4,512,32,32]
    iwt_k<<<ceil_div(B*256*16*16, 256), 256>>>(p_ic4, p_iw4, B, 1024, 16, 16, 512, 256);
    copyskip_k<<<ceil_div(B*256*32*32, 256), 256>>>(p_c3, p_iw4, B, 256, 512, 32*32);
    // ic3 = lrelu(convd4(iw4)) : 512->256 @32
    conv3x3_k<16,32,8,true,false><<<dim3(1, 2*B, 32), 128>>>(
        p_iw4, convd4_w, convd4_b, nullptr, p_ic3, 512, 256, 32, 32);
    // iw3 = concat([c2, iwt(ic3)]) : [4,128,64,64]
    iwt_k<<<ceil_div(B*64*32*32, 256), 256>>>(p_ic3, p_iw3, B, 256, 32, 32, 128, 64);
    copyskip_k<<<ceil_div(B*64*64*64, 256), 256>>>(p_c2, p_iw3, B, 64, 128, 64*64);
    // ic2 = lrelu(convd3(iw3)) : 128->64 @64
    conv3x3_k<16,32,16,true,false><<<dim3(2, 4*B, 4), 128>>>(
        p_iw3, convd3_w, convd3_b, nullptr, p_ic2, 128, 64, 64, 64);
    // iw2 = concat([c1, iwt(ic2)]) : [4,32,128,128]
    iwt_k<<<ceil_div(B*16*64*64, 256), 256>>>(p_ic2, p_iw2, B, 64, 64, 64, 32, 16);
    copyskip_k<<<ceil_div(B*16*128*128, 256), 256>>>(p_c1, p_iw2, B, 16, 32, 128*128);
    // ic1 = lrelu(convd2(iw2)) : 32->16 @128
    conv3x3_k<16,32,16,true,false><<<dim3(4, 8*B, 1), 128>>>(
        p_iw2, convd2_w, convd2_b, nullptr, p_ic1, 32, 16, 128, 128);
    // iw1 = lrelu(convd1(ic1)) : 16->12 @128
    conv3x3_k<16,32,12,true,false><<<dim3(4, 8*B, 1), 128>>>(
        p_ic1, convd1_w, convd1_b, nullptr, p_iw1, 16, 12, 128, 128);

    // y = iwt(iw1); out = cfin @ y  (fused)
    final_k<<<ceil_div(B*128*128, 256), 256>>>(p_iw1, cfin_w, out, B);
}

// round 2
// speedup vs baseline: 1.2500x; 1.2500x over previous
#include <cuda_runtime.h>
#include <cstdint>

typedef unsigned long long ull;

// ---------------------------------------------------------------------------
// Scratch buffers (device globals; no allocation allowed)
// ---------------------------------------------------------------------------
__device__ float g_w1 [786432];    // [4,12,128,128]
__device__ float g_c1 [1048576];   // [4,16,128,128]
__device__ float g_w2 [1048576];   // [4,64,64,64]
__device__ float g_c2 [1048576];   // [4,64,64,64]
__device__ float g_w3 [1048576];   // [4,256,32,32]
__device__ float g_c3 [1048576];   // [4,256,32,32]
__device__ float g_w4 [1048576];   // [4,1024,16,16]
__device__ float g_c4 [1048576];
__device__ float g_c5 [1048576];
__device__ float g_ic4[1048576];
__device__ float g_iw4[2097152];   // [4,512,32,32]
__device__ float g_ic3[1048576];   // [4,256,32,32]
__device__ float g_iw3[2097152];   // [4,128,64,64]
__device__ float g_ic2[1048576];   // [4,64,64,64]
__device__ float g_iw2[2097152];   // [4,32,128,128]
__device__ float g_ic1[1048576];   // [4,16,128,128]
__device__ float g_iw1[786432];    // [4,12,128,128]

// ---------------------------------------------------------------------------
// f32x2 packed helpers (Blackwell)
// ---------------------------------------------------------------------------
__device__ __forceinline__ ull pk(float x, float y) {
    ull r;
    asm("mov.b64 %0, {%1, %2};" : "=l"(r) : "f"(x), "f"(y));
    return r;
}
__device__ __forceinline__ void upk(float& x, float& y, ull v) {
    asm("mov.b64 {%0, %1}, %2;" : "=f"(x), "=f"(y) : "l"(v));
}
__device__ __forceinline__ void fma2(ull& d, ull a, ull b) {
    asm("fma.rn.f32x2 %0, %1, %2, %0;" : "+l"(d) : "l"(a), "l"(b));
}

// ---------------------------------------------------------------------------
// Haar DWT: in[B,C,H,W] -> out[B,4C,H/2,W/2]
// ---------------------------------------------------------------------------
__global__ void wt_k(const float* __restrict__ in, float* __restrict__ out,
                     int B, int C, int H, int W) {
    int Ho = H >> 1, Wo = W >> 1;
    int total = B * C * Ho * Wo;
    int i = blockIdx.x * blockDim.x + threadIdx.x;
    if (i >= total) return;
    int w = i % Wo;
    int h = (i / Wo) % Ho;
    int c = (i / (Wo * Ho)) % C;
    int b = i / (Wo * Ho * C);
    const float* p = in + ((size_t)(b * C + c) * H + 2 * h) * W + 2 * w;
    float a  = p[0], bb = p[1], cc = p[W], d = p[W + 1];
    float ll = 0.25f * (a + bb + cc + d);
    float hl = 0.5f  * (a + bb - cc - d);
    float lh = 0.5f  * (a - bb + cc - d);
    float hh = 0.5f  * (a - bb - cc + d);
    size_t ob = ((size_t)(b * 4 * C + 4 * c) * Ho + h) * Wo + w;
    size_t cs = (size_t)Ho * Wo;
    out[ob]          = ll;
    out[ob + cs]     = (hl + 1.f) * 0.5f;
    out[ob + 2 * cs] = (lh + 1.f) * 0.5f;
    out[ob + 3 * cs] = (hh + 1.f) * 0.5f;
}

// ---------------------------------------------------------------------------
// Haar IWT into concat buffer at channel offset
// ---------------------------------------------------------------------------
__global__ void iwt_k(const float* __restrict__ in, float* __restrict__ out,
                      int B, int C4, int H, int W, int Ctot, int coff) {
    int C = C4 >> 2;
    int total = B * C * H * W;
    int i = blockIdx.x * blockDim.x + threadIdx.x;
    if (i >= total) return;
    int w = i % W;
    int h = (i / W) % H;
    int c = (i / (W * H)) % C;
    int b = i / (W * H * C);
    size_t ib = ((size_t)(b * C4 + 4 * c) * H + h) * W + w;
    size_t cs = (size_t)H * W;
    float v0 = in[ib];
    float v1 = 2.f * in[ib + cs]     - 1.f;
    float v2 = 2.f * in[ib + 2 * cs] - 1.f;
    float v3 = 2.f * in[ib + 3 * cs] - 1.f;
    float x00 = v0 + 0.5f * ( v1 + v2 + v3);
    float x01 = v0 + 0.5f * ( v1 - v2 - v3);
    float x10 = v0 + 0.5f * (-v1 + v2 - v3);
    float x11 = v0 + 0.5f * (-v1 - v2 + v3);
    int W2 = 2 * W;
    size_t ob = ((size_t)(b * Ctot + coff + c) * 2 * H + 2 * h) * W2 + 2 * w;
    out[ob]          = x00;
    out[ob + 1]      = x01;
    out[ob + W2]     = x10;
    out[ob + W2 + 1] = x11;
}

__global__ void copyskip_k(const float* __restrict__ src, float* __restrict__ dst,
                           int B, int Csrc, int Ctot, int HW) {
    int total = B * Csrc * HW;
    int i = blockIdx.x * blockDim.x + threadIdx.x;
    if (i >= total) return;
    int p = i % HW;
    int c = (i / HW) % Csrc;
    int b = i / (HW * Csrc);
    dst[((size_t)(b * Ctot) + c) * HW + p] = src[((size_t)(b * Csrc) + c) * HW + p];
}

// ---------------------------------------------------------------------------
// Direct 3x3 conv, pad=1. f32x2-packed inner loop.
// Each thread: 2x2 output pixels x OCB channels (pixel pair packed along w).
// Block: NIMG images x (TH x TW) spatial tile. NT = NIMG*(TH/2)*(TW/2) threads.
// IC processed in chunks of ICCHUNK per barrier round.
// ---------------------------------------------------------------------------
template <int TH, int TW, int NIMG, int ICCHUNK, int OCB, bool RELU, bool ADD>
__global__ void __launch_bounds__(NIMG * (TH / 2) * (TW / 2))
conv3x3_k(const float* __restrict__ in, const float* __restrict__ wgt,
          const float* __restrict__ bias, const float* __restrict__ addsrc,
          float* __restrict__ out, int IC, int OC, int H, int W) {
    constexpr int NT   = NIMG * (TH / 2) * (TW / 2);
    constexpr int TILE = (TH + 2) * (TW + 2);

    __shared__ __align__(16) float  s_in[NIMG * ICCHUNK * TILE];
    __shared__ __align__(16) float2 s_w [ICCHUNK * OCB * 9];

    const int tiles_h = H / TH;
    const int tile_w  = blockIdx.x;
    const int tile_h  = blockIdx.y % tiles_h;
    const int bgrp    = blockIdx.y / tiles_h;
    const int oc0     = blockIdx.z * OCB;
    const int tid     = threadIdx.x;

    constexpr int PPI = (TH / 2) * (TW / 2);
    const int img = tid / PPI;
    const int t   = tid % PPI;
    const int tx  = t % (TW / 2);
    const int ty  = t / (TW / 2);
    const int b   = bgrp * NIMG + img;
    const int w0  = tile_w * TW + 2 * tx;
    const int h0  = tile_h * TH + 2 * ty;

    ull acc[OCB][2];
#pragma unroll
    for (int o = 0; o < OCB; o++) {
        float bv = bias[oc0 + o];
        acc[o][0] = pk(bv, bv);
        acc[o][1] = pk(bv, bv);
    }

    const int gh0 = tile_h * TH - 1;
    const int gw0 = tile_w * TW - 1;

    for (int ic0 = 0; ic0 < IC; ic0 += ICCHUNK) {
        // ---- cooperative load: NIMG*ICCHUNK input tiles with halo ----
        for (int i = tid; i < NIMG * ICCHUNK * TILE; i += NT) {
            int e   = i % TILE;
            int ii  = i / TILE;
            int icc = ii % ICCHUNK;
            int im  = ii / ICCHUNK;
            int r   = e / (TW + 2);
            int cq  = e % (TW + 2);
            int gh  = gh0 + r;
            int gw  = gw0 + cq;
            float v = 0.f;
            if ((unsigned)gh < (unsigned)H && (unsigned)gw < (unsigned)W)
                v = in[((size_t)((bgrp * NIMG + im) * IC + ic0 + icc) * H + gh) * W + gw];
            s_in[i] = v;
        }
        // ---- weights, duplicated into float2 for f32x2 FMA ----
        for (int i = tid; i < ICCHUNK * OCB * 9; i += NT) {
            int j   = i % 9;
            int o   = (i / 9) % OCB;
            int icc = i / (9 * OCB);
            float v = wgt[((size_t)(oc0 + o) * IC + ic0 + icc) * 9 + j];
            s_w[(icc * OCB + o) * 9 + j] = make_float2(v, v);
        }
        __syncthreads();

#pragma unroll
        for (int icc = 0; icc < ICCHUNK; icc++) {
            const float* tile = &s_in[(img * ICCHUNK + icc) * TILE];
            ull rp[4][3];
#pragma unroll
            for (int di = 0; di < 4; di++) {
                const float2* p = (const float2*)(tile + (2 * ty + di) * (TW + 2) + 2 * tx);
                float2 a = p[0];
                float2 bq = p[1];
                rp[di][0] = pk(a.x, a.y);
                rp[di][1] = pk(a.y, bq.x);
                rp[di][2] = pk(bq.x, bq.y);
            }
#pragma unroll
            for (int o = 0; o < OCB; o++) {
                const ull* wp = (const ull*)&s_w[(icc * OCB + o) * 9];
#pragma unroll
                for (int ki = 0; ki < 3; ki++)
#pragma unroll
                    for (int kj = 0; kj < 3; kj++) {
                        ull w = wp[ki * 3 + kj];
                        fma2(acc[o][0], rp[ki][kj],     w);
                        fma2(acc[o][1], rp[ki + 1][kj], w);
                    }
            }
        }
        __syncthreads();
    }

#pragma unroll
    for (int o = 0; o < OCB; o++) {
        size_t base = ((size_t)(b * OC + oc0 + o) * H + h0) * W + w0;
#pragma unroll
        for (int pi = 0; pi < 2; pi++) {
            float x, y;
            upk(x, y, acc[o][pi]);
            if (ADD) {
                float2 s = *(const float2*)&addsrc[base + (size_t)pi * W];
                x += s.x; y += s.y;
            }
            if (RELU) {
                x = (x >= 0.f) ? x : 0.2f * x;
                y = (y >= 0.f) ? y : 0.2f * y;
            }
            *(float2*)&out[base + (size_t)pi * W] = make_float2(x, y);
        }
    }
}

// ---------------------------------------------------------------------------
// Final: y = iwt(iw1[4,12,128,128]); out = 1x1 conv cfin @ y -> [4,3,256,256]
// ---------------------------------------------------------------------------
__global__ void final_k(const float* __restrict__ in, const float* __restrict__ cfin,
                        float* __restrict__ out, int B) {
    const int H = 128, W = 128;
    int total = B * H * W;
    int i = blockIdx.x * blockDim.x + threadIdx.x;
    if (i >= total) return;
    int w = i % W;
    int h = (i / W) % H;
    int b = i / (W * H);

    float y00[3], y01[3], y10[3], y11[3];
#pragma unroll
    for (int c = 0; c < 3; c++) {
        size_t ib = ((size_t)(b * 12 + 4 * c) * H + h) * W + w;
        size_t cs = (size_t)H * W;
        float v0 = in[ib];
        float v1 = 2.f * in[ib + cs]     - 1.f;
        float v2 = 2.f * in[ib + 2 * cs] - 1.f;
        float v3 = 2.f * in[ib + 3 * cs] - 1.f;
        y00[c] = v0 + 0.5f * ( v1 + v2 + v3);
        y01[c] = v0 + 0.5f * ( v1 - v2 - v3);
        y10[c] = v0 + 0.5f * (-v1 + v2 - v3);
        y11[c] = v0 + 0.5f * (-v1 - v2 + v3);
    }
    float m[9];
#pragma unroll
    for (int j = 0; j < 9; j++) m[j] = cfin[j];

    const int HO = 256, WO = 256;
#pragma unroll
    for (int o = 0; o < 3; o++) {
        float o00 = m[o*3+0]*y00[0] + m[o*3+1]*y00[1] + m[o*3+2]*y00[2];
        float o01 = m[o*3+0]*y01[0] + m[o*3+1]*y01[1] + m[o*3+2]*y01[2];
        float o10 = m[o*3+0]*y10[0] + m[o*3+1]*y10[1] + m[o*3+2]*y10[2];
        float o11 = m[o*3+0]*y11[0] + m[o*3+1]*y11[1] + m[o*3+2]*y11[2];
        size_t ob = ((size_t)(b * 3 + o) * HO + 2 * h) * WO + 2 * w;
        out[ob]          = o00;
        out[ob + 1]      = o01;
        out[ob + WO]     = o10;
        out[ob + WO + 1] = o11;
    }
}

// ---------------------------------------------------------------------------
// Host side
// ---------------------------------------------------------------------------
static inline int ceil_div(int a, int b) { return (a + b - 1) / b; }

extern "C" void kernel_launch(void* const* d_in, const int* in_sizes, int n_in,
                              void* d_out, int out_size) {
    (void)in_sizes; (void)n_in; (void)out_size;
    const float* x        = (const float*)d_in[0];
    const float* conv1_w  = (const float*)d_in[1];
    const float* conv1_b  = (const float*)d_in[2];
    const float* conv2_w  = (const float*)d_in[3];
    const float* conv2_b  = (const float*)d_in[4];
    const float* conv3_w  = (const float*)d_in[5];
    const float* conv3_b  = (const float*)d_in[6];
    const float* conv4_w  = (const float*)d_in[7];
    const float* conv4_b  = (const float*)d_in[8];
    const float* convd4_w = (const float*)d_in[9];
    const float* convd4_b = (const float*)d_in[10];
    const float* convd3_w = (const float*)d_in[11];
    const float* convd3_b = (const float*)d_in[12];
    const float* convd2_w = (const float*)d_in[13];
    const float* convd2_b = (const float*)d_in[14];
    const float* convd1_w = (const float*)d_in[15];
    const float* convd1_b = (const float*)d_in[16];
    const float* cfin_w   = (const float*)d_in[17];
    float* out = (float*)d_out;

    static float *p_w1=nullptr,*p_c1,*p_w2,*p_c2,*p_w3,*p_c3,*p_w4,*p_c4,*p_c5,
                 *p_ic4,*p_iw4,*p_ic3,*p_iw3,*p_ic2,*p_iw2,*p_ic1,*p_iw1;
    if (!p_w1) {
        cudaGetSymbolAddress((void**)&p_w1,  g_w1);
        cudaGetSymbolAddress((void**)&p_c1,  g_c1);
        cudaGetSymbolAddress((void**)&p_w2,  g_w2);
        cudaGetSymbolAddress((void**)&p_c2,  g_c2);
        cudaGetSymbolAddress((void**)&p_w3,  g_w3);
        cudaGetSymbolAddress((void**)&p_c3,  g_c3);
        cudaGetSymbolAddress((void**)&p_w4,  g_w4);
        cudaGetSymbolAddress((void**)&p_c4,  g_c4);
        cudaGetSymbolAddress((void**)&p_c5,  g_c5);
        cudaGetSymbolAddress((void**)&p_ic4, g_ic4);
        cudaGetSymbolAddress((void**)&p_iw4, g_iw4);
        cudaGetSymbolAddress((void**)&p_ic3, g_ic3);
        cudaGetSymbolAddress((void**)&p_iw3, g_iw3);
        cudaGetSymbolAddress((void**)&p_ic2, g_ic2);
        cudaGetSymbolAddress((void**)&p_iw2, g_iw2);
        cudaGetSymbolAddress((void**)&p_ic1, g_ic1);
        cudaGetSymbolAddress((void**)&p_iw1, g_iw1);
    }

    const int B = 4;

    // ---- encoder ----
    wt_k<<<ceil_div(B*3*128*128, 256), 256>>>(x, p_w1, B, 3, 256, 256);

    // conv1: 12->16 @128x128. tiles 4x4, OCB=8 -> grid (4,16,2)=128 blocks x256
    conv3x3_k<32,32,1,4,8,true,false><<<dim3(4, 4*B, 2), 256>>>(
        p_w1, conv1_w, conv1_b, nullptr, p_c1, 12, 16, 128, 128);

    wt_k<<<ceil_div(B*16*64*64, 256), 256>>>(p_c1, p_w2, B, 16, 128, 128);

    // conv2: 64->64 @64x64. tiles 2x2, OCB=4 -> grid (2,8,16)=256 blocks x256
    conv3x3_k<32,32,1,8,4,true,false><<<dim3(2, 2*B, 16), 256>>>(
        p_w2, conv2_w, conv2_b, nullptr, p_c2, 64, 64, 64, 64);

    wt_k<<<ceil_div(B*64*32*32, 256), 256>>>(p_c2, p_w3, B, 64, 64, 64);

    // conv3: 256->256 @32x32. full-image tile, OCB=4 -> grid (1,4,64)=256 blocks
    conv3x3_k<32,32,1,8,4,true,false><<<dim3(1, 1*B, 64), 256>>>(
        p_w3, conv3_w, conv3_b, nullptr, p_c3, 256, 256, 32, 32);

    wt_k<<<ceil_div(B*256*16*16, 256), 256>>>(p_c3, p_w4, B, 256, 32, 32);

    // ---- bottleneck: three conv4 1024->1024 @16x16 ----
    // NIMG=2, OCB=8 -> grid (1, 2, 128) = 256 blocks x 128 threads
    conv3x3_k<16,16,2,8,8,true,false><<<dim3(1, 2, 128), 128>>>(
        p_w4, conv4_w, conv4_b, nullptr, p_c4, 1024, 1024, 16, 16);
    conv3x3_k<16,16,2,8,8,true,false><<<dim3(1, 2, 128), 128>>>(
        p_c4, conv4_w, conv4_b, nullptr, p_c5, 1024, 1024, 16, 16);
    conv3x3_k<16,16,2,8,8,true,true><<<dim3(1, 2, 128), 128>>>(
        p_c5, conv4_w, conv4_b, p_w4, p_ic4, 1024, 1024, 16, 16);

    // ---- decoder ----
    iwt_k<<<ceil_div(B*256*16*16, 256), 256>>>(p_ic4, p_iw4, B, 1024, 16, 16, 512, 256);
    copyskip_k<<<ceil_div(B*256*32*32, 256), 256>>>(p_c3, p_iw4, B, 256, 512, 32*32);

    // convd4: 512->256 @32x32. OCB=4 -> grid (1,4,64)=256 blocks
    conv3x3_k<32,32,1,8,4,true,false><<<dim3(1, 1*B, 64), 256>>>(
        p_iw4, convd4_w, convd4_b, nullptr, p_ic3, 512, 256, 32, 32);

    iwt_k<<<ceil_div(B*64*32*32, 256), 256>>>(p_ic3, p_iw3, B, 256, 32, 32, 128, 64);
    copyskip_k<<<ceil_div(B*64*64*64, 256), 256>>>(p_c2, p_iw3, B, 64, 128, 64*64);

    // convd3: 128->64 @64x64. OCB=4 -> grid (2,8,16)=256 blocks
    conv3x3_k<32,32,1,8,4,true,false><<<dim3(2, 2*B, 16), 256>>>(
        p_iw3, convd3_w, convd3_b, nullptr, p_ic2, 128, 64, 64, 64);

    iwt_k<<<ceil_div(B*16*64*64, 256), 256>>>(p_ic2, p_iw2, B, 64, 64, 64, 32, 16);
    copyskip_k<<<ceil_div(B*16*128*128, 256), 256>>>(p_c1, p_iw2, B, 16, 32, 128*128);

    // convd2: 32->16 @128x128. OCB=4 -> grid (4,16,4)=256 blocks
    conv3x3_k<32,32,1,8,4,true,false><<<dim3(4, 4*B, 4), 256>>>(
        p_iw2, convd2_w, convd2_b, nullptr, p_ic1, 32, 16, 128, 128);

    // convd1: 16->12 @128x128. OCB=4 -> grid (4,16,3)=192 blocks
    conv3x3_k<32,32,1,8,4,true,false><<<dim3(4, 4*B, 3), 256>>>(
        p_ic1, convd1_w, convd1_b, nullptr, p_iw1, 16, 12, 128, 128);

    // fused final iwt + 1x1
    final_k<<<ceil_div(B*128*128, 256), 256>>>(p_iw1, cfin_w, out, B);
}

// round 3
// speedup vs baseline: 1.8714x; 1.4971x over previous
#include <cuda_runtime.h>
#include <cstdint>

typedef unsigned long long ull;

// ---------------------------------------------------------------------------
// Scratch buffers (device globals; no allocation allowed)
// ---------------------------------------------------------------------------
__device__ float g_w1 [786432];    // [4,12,128,128]
__device__ float g_c1 [1048576];   // [4,16,128,128]
__device__ float g_w2 [1048576];   // [4,64,64,64]
__device__ float g_c2 [1048576];   // [4,64,64,64]
__device__ float g_w3 [1048576];   // [4,256,32,32]
__device__ float g_c3 [1048576];   // [4,256,32,32]
__device__ float g_w4 [1048576];   // [4,1024,16,16]
__device__ float g_c4 [1048576];
__device__ float g_c5 [1048576];
__device__ float g_ic4[1048576];
__device__ float g_iw4[2097152];   // [4,512,32,32]
__device__ float g_ic3[1048576];   // [4,256,32,32]
__device__ float g_iw3[2097152];   // [4,128,64,64]
__device__ float g_ic2[1048576];   // [4,64,64,64]
__device__ float g_iw2[2097152];   // [4,32,128,128]
__device__ float g_ic1[1048576];   // [4,16,128,128]
__device__ float g_iw1[786432];    // [4,12,128,128]

// ---------------------------------------------------------------------------
// f32x2 packed helpers (Blackwell FFMA2)
// ---------------------------------------------------------------------------
__device__ __forceinline__ ull pk(float x, float y) {
    ull r;
    asm("mov.b64 %0, {%1, %2};" : "=l"(r) : "f"(x), "f"(y));
    return r;
}
__device__ __forceinline__ void upk(float& x, float& y, ull v) {
    asm("mov.b64 {%0, %1}, %2;" : "=f"(x), "=f"(y) : "l"(v));
}
__device__ __forceinline__ void fma2(ull& d, ull a, ull b) {
    asm("fma.rn.f32x2 %0, %1, %2, %0;" : "+l"(d) : "l"(a), "l"(b));
}

// ---------------------------------------------------------------------------
// Haar DWT: in[B,C,H,W] -> out[B,4C,H/2,W/2]
// ---------------------------------------------------------------------------
__global__ void wt_k(const float* __restrict__ in, float* __restrict__ out,
                     int B, int C, int H, int W) {
    int Ho = H >> 1, Wo = W >> 1;
    int total = B * C * Ho * Wo;
    int i = blockIdx.x * blockDim.x + threadIdx.x;
    if (i >= total) return;
    int w = i % Wo;
    int h = (i / Wo) % Ho;
    int c = (i / (Wo * Ho)) % C;
    int b = i / (Wo * Ho * C);
    const float* p = in + ((size_t)(b * C + c) * H + 2 * h) * W + 2 * w;
    float a  = p[0], bb = p[1], cc = p[W], d = p[W + 1];
    float ll = 0.25f * (a + bb + cc + d);
    float hl = 0.5f  * (a + bb - cc - d);
    float lh = 0.5f  * (a - bb + cc - d);
    float hh = 0.5f  * (a - bb - cc + d);
    size_t ob = ((size_t)(b * 4 * C + 4 * c) * Ho + h) * Wo + w;
    size_t cs = (size_t)Ho * Wo;
    out[ob]          = ll;
    out[ob + cs]     = (hl + 1.f) * 0.5f;
    out[ob + 2 * cs] = (lh + 1.f) * 0.5f;
    out[ob + 3 * cs] = (hh + 1.f) * 0.5f;
}

// ---------------------------------------------------------------------------
// Haar IWT into concat buffer at channel offset
// ---------------------------------------------------------------------------
__global__ void iwt_k(const float* __restrict__ in, float* __restrict__ out,
                      int B, int C4, int H, int W, int Ctot, int coff) {
    int C = C4 >> 2;
    int total = B * C * H * W;
    int i = blockIdx.x * blockDim.x + threadIdx.x;
    if (i >= total) return;
    int w = i % W;
    int h = (i / W) % H;
    int c = (i / (W * H)) % C;
    int b = i / (W * H * C);
    size_t ib = ((size_t)(b * C4 + 4 * c) * H + h) * W + w;
    size_t cs = (size_t)H * W;
    float v0 = in[ib];
    float v1 = 2.f * in[ib + cs]     - 1.f;
    float v2 = 2.f * in[ib + 2 * cs] - 1.f;
    float v3 = 2.f * in[ib + 3 * cs] - 1.f;
    float x00 = v0 + 0.5f * ( v1 + v2 + v3);
    float x01 = v0 + 0.5f * ( v1 - v2 - v3);
    float x10 = v0 + 0.5f * (-v1 + v2 - v3);
    float x11 = v0 + 0.5f * (-v1 - v2 + v3);
    int W2 = 2 * W;
    size_t ob = ((size_t)(b * Ctot + coff + c) * 2 * H + 2 * h) * W2 + 2 * w;
    out[ob]          = x00;
    out[ob + 1]      = x01;
    out[ob + W2]     = x10;
    out[ob + W2 + 1] = x11;
}

__global__ void copyskip_k(const float* __restrict__ src, float* __restrict__ dst,
                           int B, int Csrc, int Ctot, int HW) {
    int total = B * Csrc * HW;
    int i = blockIdx.x * blockDim.x + threadIdx.x;
    if (i >= total) return;
    int p = i % HW;
    int c = (i / HW) % Csrc;
    int b = i / (HW * Csrc);
    dst[((size_t)(b * Ctot) + c) * HW + p] = src[((size_t)(b * Csrc) + c) * HW + p];
}

// ---------------------------------------------------------------------------
// Direct 3x3 conv, pad=1. f32x2-packed, 4x2 output pixels per thread.
// Block: NIMG images x (TH x TW) tile. PPI = (TH/4)*(TW/2) threads per image.
// Tile fill: interior via aligned float4 (shift/mask indexing only), halo via
// compare-based mapping — no integer division anywhere in the hot loop.
// ---------------------------------------------------------------------------
template <int TH, int TW, int NIMG, int ICCHUNK, int OCB, bool RELU, bool ADD>
__global__ void __launch_bounds__(NIMG * (TH / 4) * (TW / 2))
conv3x3_k(const float* __restrict__ in, const float* __restrict__ wgt,
          const float* __restrict__ bias, const float* __restrict__ addsrc,
          float* __restrict__ out, int IC, int OC, int H, int W) {
    constexpr int PPI  = (TH / 4) * (TW / 2);
    constexpr int NT   = NIMG * PPI;
    constexpr int RS   = TW + 2;          // smem row stride (even)
    constexpr int TILE = (TH + 2) * RS;
    constexpr int C4   = TW / 4;          // float4 groups per row (pow2)
    constexpr int N4   = TH * TW / 4;     // interior float4 count
    constexpr int HN   = 2 * RS + 2 * TH; // halo element count

    __shared__ __align__(16) float  s_in[NIMG * ICCHUNK * TILE];
    __shared__ __align__(16) float2 s_w [ICCHUNK * OCB * 9];

    const int tiles_h = H / TH;
    const int tile_w  = blockIdx.x;
    const int tile_h  = blockIdx.y % tiles_h;
    const int bgrp    = blockIdx.y / tiles_h;
    const int oc0     = blockIdx.z * OCB;
    const int tid     = threadIdx.x;
    const int img     = tid / PPI;        // pow2
    const int lt      = tid % PPI;
    const int tx      = lt % (TW / 2);    // pow2
    const int ty      = lt / (TW / 2);
    const int b       = bgrp * NIMG + img;
    const int h0      = tile_h * TH + 4 * ty;
    const int w0      = tile_w * TW + 2 * tx;
    const int ghbase  = tile_h * TH;
    const int gwbase  = tile_w * TW;

    ull acc[OCB][4];
#pragma unroll
    for (int o = 0; o < OCB; o++) {
        float bv = bias[oc0 + o];
#pragma unroll
        for (int r = 0; r < 4; r++) acc[o][r] = pk(bv, bv);
    }

    for (int ic0 = 0; ic0 < IC; ic0 += ICCHUNK) {
        // ---- fill NIMG*ICCHUNK tiles (each image's threads fill its own) ----
        const float* inb = in + ((size_t)b * IC + ic0) * H * W;
        float* tb0 = s_in + img * ICCHUNK * TILE;
        for (int icc = 0; icc < ICCHUNK; icc++) {
            const float* inc = inb + (size_t)icc * H * W;
            float* tb = tb0 + icc * TILE;
            // interior: aligned float4 loads, shift/mask indexing
#pragma unroll
            for (int i0 = 0; i0 < N4; i0 += PPI) {
                int i = i0 + lt;
                int r = i / C4;           // pow2 shift
                int c = i & (C4 - 1);
                float4 v = *(const float4*)&inc[(size_t)(ghbase + r) * W + gwbase + 4 * c];
                float* d = tb + (r + 1) * RS + 1 + 4 * c;
                d[0] = v.x; d[1] = v.y; d[2] = v.z; d[3] = v.w;
            }
            // halo: compare-based mapping, zero-pad out of bounds
            for (int i = lt; i < HN; i += PPI) {
                int sr, sc;
                if (i < RS)               { sr = 0;               sc = i;           }
                else if (i < 2 * RS)      { sr = TH + 1;          sc = i - RS;      }
                else if (i < 2 * RS + TH) { sr = i - 2 * RS + 1;  sc = 0;           }
                else                      { sr = i - 2 * RS - TH + 1; sc = TW + 1;  }
                int gh = ghbase + sr - 1;
                int gw = gwbase + sc - 1;
                float v = 0.f;
                if ((unsigned)gh < (unsigned)H && (unsigned)gw < (unsigned)W)
                    v = inc[(size_t)gh * W + gw];
                tb[sr * RS + sc] = v;
            }
        }
        // ---- weights (duplicated into float2 lanes for FFMA2) ----
        for (int i = tid; i < ICCHUNK * OCB * 9; i += NT) {
            int j   = i % 9;
            int o   = (i / 9) % OCB;
            int icc = i / (9 * OCB);
            float v = wgt[((size_t)(oc0 + o) * IC + ic0 + icc) * 9 + j];
            s_w[(icc * OCB + o) * 9 + j] = make_float2(v, v);
        }
        __syncthreads();

#pragma unroll 2
        for (int icc = 0; icc < ICCHUNK; icc++) {
            const float* tile = s_in + (img * ICCHUNK + icc) * TILE;
            // 6 input rows x 3 packed column-shifts
            ull rp[6][3];
#pragma unroll
            for (int r = 0; r < 6; r++) {
                const float2* p = (const float2*)(tile + (4 * ty + r) * RS + 2 * tx);
                float2 a = p[0], bq = p[1];
                rp[r][0] = pk(a.x, a.y);
                rp[r][1] = pk(a.y, bq.x);
                rp[r][2] = pk(bq.x, bq.y);
            }
#pragma unroll
            for (int o = 0; o < OCB; o++) {
                const ull* wp = (const ull*)&s_w[(icc * OCB + o) * 9];
#pragma unroll
                for (int ki = 0; ki < 3; ki++)
#pragma unroll
                    for (int kj = 0; kj < 3; kj++) {
                        ull w = wp[ki * 3 + kj];
                        fma2(acc[o][0], rp[ki][kj],     w);
                        fma2(acc[o][1], rp[ki + 1][kj], w);
                        fma2(acc[o][2], rp[ki + 2][kj], w);
                        fma2(acc[o][3], rp[ki + 3][kj], w);
                    }
            }
        }
        __syncthreads();
    }

#pragma unroll
    for (int o = 0; o < OCB; o++) {
        size_t base = ((size_t)(b * OC + oc0 + o) * H + h0) * W + w0;
#pragma unroll
        for (int r = 0; r < 4; r++) {
            float x, y;
            upk(x, y, acc[o][r]);
            if (ADD) {
                float2 s = *(const float2*)&addsrc[base + (size_t)r * W];
                x += s.x; y += s.y;
            }
            if (RELU) {
                x = (x >= 0.f) ? x : 0.2f * x;
                y = (y >= 0.f) ? y : 0.2f * y;
            }
            *(float2*)&out[base + (size_t)r * W] = make_float2(x, y);
        }
    }
}

// ---------------------------------------------------------------------------
// Final: y = iwt(iw1[4,12,128,128]); out = 1x1 conv cfin @ y -> [4,3,256,256]
// ---------------------------------------------------------------------------
__global__ void final_k(const float* __restrict__ in, const float* __restrict__ cfin,
                        float* __restrict__ out, int B) {
    const int H = 128, W = 128;
    int total = B * H * W;
    int i = blockIdx.x * blockDim.x + threadIdx.x;
    if (i >= total) return;
    int w = i % W;
    int h = (i / W) % H;
    int b = i / (W * H);

    float y00[3], y01[3], y10[3], y11[3];
#pragma unroll
    for (int c = 0; c < 3; c++) {
        size_t ib = ((size_t)(b * 12 + 4 * c) * H + h) * W + w;
        size_t cs = (size_t)H * W;
        float v0 = in[ib];
        float v1 = 2.f * in[ib + cs]     - 1.f;
        float v2 = 2.f * in[ib + 2 * cs] - 1.f;
        float v3 = 2.f * in[ib + 3 * cs] - 1.f;
        y00[c] = v0 + 0.5f * ( v1 + v2 + v3);
        y01[c] = v0 + 0.5f * ( v1 - v2 - v3);
        y10[c] = v0 + 0.5f * (-v1 + v2 - v3);
        y11[c] = v0 + 0.5f * (-v1 - v2 + v3);
    }
    float m[9];
#pragma unroll
    for (int j = 0; j < 9; j++) m[j] = cfin[j];

    const int HO = 256, WO = 256;
#pragma unroll
    for (int o = 0; o < 3; o++) {
        float o00 = m[o*3+0]*y00[0] + m[o*3+1]*y00[1] + m[o*3+2]*y00[2];
        float o01 = m[o*3+0]*y01[0] + m[o*3+1]*y01[1] + m[o*3+2]*y01[2];
        float o10 = m[o*3+0]*y10[0] + m[o*3+1]*y10[1] + m[o*3+2]*y10[2];
        float o11 = m[o*3+0]*y11[0] + m[o*3+1]*y11[1] + m[o*3+2]*y11[2];
        size_t ob = ((size_t)(b * 3 + o) * HO + 2 * h) * WO + 2 * w;
        out[ob]          = o00;
        out[ob + 1]      = o01;
        out[ob + WO]     = o10;
        out[ob + WO + 1] = o11;
    }
}

// ---------------------------------------------------------------------------
// Host side
// ---------------------------------------------------------------------------
static inline int ceil_div(int a, int b) { return (a + b - 1) / b; }

extern "C" void kernel_launch(void* const* d_in, const int* in_sizes, int n_in,
                              void* d_out, int out_size) {
    (void)in_sizes; (void)n_in; (void)out_size;
    const float* x        = (const float*)d_in[0];
    const float* conv1_w  = (const float*)d_in[1];
    const float* conv1_b  = (const float*)d_in[2];
    const float* conv2_w  = (const float*)d_in[3];
    const float* conv2_b  = (const float*)d_in[4];
    const float* conv3_w  = (const float*)d_in[5];
    const float* conv3_b  = (const float*)d_in[6];
    const float* conv4_w  = (const float*)d_in[7];
    const float* conv4_b  = (const float*)d_in[8];
    const float* convd4_w = (const float*)d_in[9];
    const float* convd4_b = (const float*)d_in[10];
    const float* convd3_w = (const float*)d_in[11];
    const float* convd3_b = (const float*)d_in[12];
    const float* convd2_w = (const float*)d_in[13];
    const float* convd2_b = (const float*)d_in[14];
    const float* convd1_w = (const float*)d_in[15];
    const float* convd1_b = (const float*)d_in[16];
    const float* cfin_w   = (const float*)d_in[17];
    float* out = (float*)d_out;

    static float *p_w1=nullptr,*p_c1,*p_w2,*p_c2,*p_w3,*p_c3,*p_w4,*p_c4,*p_c5,
                 *p_ic4,*p_iw4,*p_ic3,*p_iw3,*p_ic2,*p_iw2,*p_ic1,*p_iw1;
    if (!p_w1) {
        cudaGetSymbolAddress((void**)&p_w1,  g_w1);
        cudaGetSymbolAddress((void**)&p_c1,  g_c1);
        cudaGetSymbolAddress((void**)&p_w2,  g_w2);
        cudaGetSymbolAddress((void**)&p_c2,  g_c2);
        cudaGetSymbolAddress((void**)&p_w3,  g_w3);
        cudaGetSymbolAddress((void**)&p_c3,  g_c3);
        cudaGetSymbolAddress((void**)&p_w4,  g_w4);
        cudaGetSymbolAddress((void**)&p_c4,  g_c4);
        cudaGetSymbolAddress((void**)&p_c5,  g_c5);
        cudaGetSymbolAddress((void**)&p_ic4, g_ic4);
        cudaGetSymbolAddress((void**)&p_iw4, g_iw4);
        cudaGetSymbolAddress((void**)&p_ic3, g_ic3);
        cudaGetSymbolAddress((void**)&p_iw3, g_iw3);
        cudaGetSymbolAddress((void**)&p_ic2, g_ic2);
        cudaGetSymbolAddress((void**)&p_iw2, g_iw2);
        cudaGetSymbolAddress((void**)&p_ic1, g_ic1);
        cudaGetSymbolAddress((void**)&p_iw1, g_iw1);
    }

    const int B = 4;

    // ---- encoder ----
    wt_k<<<ceil_div(B*3*128*128, 256), 256>>>(x, p_w1, B, 3, 256, 256);

    // conv1: 12->16 @128x128. TH32 TW32, ICCHUNK=12, OCB=4. grid (4,16,4)=256 x128
    conv3x3_k<32,32,1,12,4,true,false><<<dim3(4, 4*B, 4), 128>>>(
        p_w1, conv1_w, conv1_b, nullptr, p_c1, 12, 16, 128, 128);

    wt_k<<<ceil_div(B*16*64*64, 256), 256>>>(p_c1, p_w2, B, 16, 128, 128);

    // conv2: 64->64 @64x64. grid (2,8,16)=256 x128
    conv3x3_k<32,32,1,8,4,true,false><<<dim3(2, 2*B, 16), 128>>>(
        p_w2, conv2_w, conv2_b, nullptr, p_c2, 64, 64, 64, 64);

    wt_k<<<ceil_div(B*64*32*32, 256), 256>>>(p_c2, p_w3, B, 64, 64, 64);

    // conv3: 256->256 @32x32. grid (1,4,64)=256 x128
    conv3x3_k<32,32,1,8,4,true,false><<<dim3(1, 1*B, 64), 128>>>(
        p_w3, conv3_w, conv3_b, nullptr, p_c3, 256, 256, 32, 32);

    wt_k<<<ceil_div(B*256*16*16, 256), 256>>>(p_c3, p_w4, B, 256, 32, 32);

    // ---- bottleneck: three conv4 1024->1024 @16x16 ----
    // TH16 TW16, NIMG=4 (whole batch per block), OCB=4 -> grid (1,1,256)=256 x128
    conv3x3_k<16,16,4,8,4,true,false><<<dim3(1, 1, 256), 128>>>(
        p_w4, conv4_w, conv4_b, nullptr, p_c4, 1024, 1024, 16, 16);
    conv3x3_k<16,16,4,8,4,true,false><<<dim3(1, 1, 256), 128>>>(
        p_c4, conv4_w, conv4_b, nullptr, p_c5, 1024, 1024, 16, 16);
    conv3x3_k<16,16,4,8,4,true,true><<<dim3(1, 1, 256), 128>>>(
        p_c5, conv4_w, conv4_b, p_w4, p_ic4, 1024, 1024, 16, 16);

    // ---- decoder ----
    iwt_k<<<ceil_div(B*256*16*16, 256), 256>>>(p_ic4, p_iw4, B, 1024, 16, 16, 512, 256);
    copyskip_k<<<ceil_div(B*256*32*32, 256), 256>>>(p_c3, p_iw4, B, 256, 512, 32*32);

    // convd4: 512->256 @32x32. grid (1,4,64)=256 x128
    conv3x3_k<32,32,1,8,4,true,false><<<dim3(1, 1*B, 64), 128>>>(
        p_iw4, convd4_w, convd4_b, nullptr, p_ic3, 512, 256, 32, 32);

    iwt_k<<<ceil_div(B*64*32*32, 256), 256>>>(p_ic3, p_iw3, B, 256, 32, 32, 128, 64);
    copyskip_k<<<ceil_div(B*64*64*64, 256), 256>>>(p_c2, p_iw3, B, 64, 128, 64*64);

    // convd3: 128->64 @64x64. grid (2,8,16)=256 x128
    conv3x3_k<32,32,1,8,4,true,false><<<dim3(2, 2*B, 16), 128>>>(
        p_iw3, convd3_w, convd3_b, nullptr, p_ic2, 128, 64, 64, 64);

    iwt_k<<<ceil_div(B*16*64*64, 256), 256>>>(p_ic2, p_iw2, B, 64, 64, 64, 32, 16);
    copyskip_k<<<ceil_div(B*16*128*128, 256), 256>>>(p_c1, p_iw2, B, 16, 32, 128*128);

    // convd2: 32->16 @128x128. grid (4,16,4)=256 x128
    conv3x3_k<32,32,1,8,4,true,false><<<dim3(4, 4*B, 4), 128>>>(
        p_iw2, convd2_w, convd2_b, nullptr, p_ic1, 32, 16, 128, 128);

    // convd1: 16->12 @128x128. grid (4,16,3)=192 x128
    conv3x3_k<32,32,1,8,4,true,false><<<dim3(4, 4*B, 3), 128>>>(
        p_ic1, convd1_w, convd1_b, nullptr, p_iw1, 16, 12, 128, 128);

    // fused final iwt + 1x1
    final_k<<<ceil_div(B*128*128, 256), 256>>>(p_iw1, cfin_w, out, B);
}

// round 4
// speedup vs baseline: 2.1397x; 1.1434x over previous
#include <cuda_runtime.h>
#include <cstdint>

typedef unsigned long long ull;

// ---------------------------------------------------------------------------
// Scratch buffers (device globals; no allocation allowed)
// ---------------------------------------------------------------------------
__device__ float g_w1 [786432];    // [4,12,128,128]
__device__ float g_c1 [1048576];   // [4,16,128,128]
__device__ float g_w2 [1048576];   // [4,64,64,64]
__device__ float g_c2 [1048576];   // [4,64,64,64]
__device__ float g_w3 [1048576];   // [4,256,32,32]
__device__ float g_c3 [1048576];   // [4,256,32,32]
__device__ float g_w4 [1048576];   // [4,1024,16,16]
__device__ float g_c4 [1048576];
__device__ float g_c5 [1048576];
__device__ float g_ic4[1048576];
__device__ float g_iw4[2097152];   // [4,512,32,32]
__device__ float g_ic3[1048576];   // [4,256,32,32]
__device__ float g_iw3[2097152];   // [4,128,64,64]
__device__ float g_ic2[1048576];   // [4,64,64,64]
__device__ float g_iw2[2097152];   // [4,32,128,128]
__device__ float g_ic1[1048576];   // [4,16,128,128]
__device__ float g_iw1[786432];    // [4,12,128,128]

// ---------------------------------------------------------------------------
// f32x2 packed helpers (Blackwell FFMA2)
// ---------------------------------------------------------------------------
__device__ __forceinline__ ull pk(float x, float y) {
    ull r;
    asm("mov.b64 %0, {%1, %2};" : "=l"(r) : "f"(x), "f"(y));
    return r;
}
__device__ __forceinline__ void upk(float& x, float& y, ull v) {
    asm("mov.b64 {%0, %1}, %2;" : "=f"(x), "=f"(y) : "l"(v));
}
__device__ __forceinline__ void fma2(ull& d, ull a, ull b) {
    asm("fma.rn.f32x2 %0, %1, %2, %0;" : "+l"(d) : "l"(a), "l"(b));
}

// ---------------------------------------------------------------------------
// Haar DWT (standalone, only for the network input x)
// ---------------------------------------------------------------------------
__global__ void wt_k(const float* __restrict__ in, float* __restrict__ out,
                     int B, int C, int H, int W) {
    int Ho = H >> 1, Wo = W >> 1;
    int total = B * C * Ho * Wo;
    int i = blockIdx.x * blockDim.x + threadIdx.x;
    if (i >= total) return;
    int w = i % Wo;
    int h = (i / Wo) % Ho;
    int c = (i / (Wo * Ho)) % C;
    int b = i / (Wo * Ho * C);
    const float* p = in + ((size_t)(b * C + c) * H + 2 * h) * W + 2 * w;
    float a  = p[0], bb = p[1], cc = p[W], d = p[W + 1];
    float ll = 0.25f * (a + bb + cc + d);
    float hl = 0.5f  * (a + bb - cc - d);
    float lh = 0.5f  * (a - bb + cc - d);
    float hh = 0.5f  * (a - bb - cc + d);
    size_t ob = ((size_t)(b * 4 * C + 4 * c) * Ho + h) * Wo + w;
    size_t cs = (size_t)Ho * Wo;
    out[ob]          = ll;
    out[ob + cs]     = (hl + 1.f) * 0.5f;
    out[ob + 2 * cs] = (lh + 1.f) * 0.5f;
    out[ob + 3 * cs] = (hh + 1.f) * 0.5f;
}

// ---------------------------------------------------------------------------
// Haar IWT into concat buffer at channel offset
// ---------------------------------------------------------------------------
__global__ void iwt_k(const float* __restrict__ in, float* __restrict__ out,
                      int B, int C4, int H, int W, int Ctot, int coff) {
    int C = C4 >> 2;
    int total = B * C * H * W;
    int i = blockIdx.x * blockDim.x + threadIdx.x;
    if (i >= total) return;
    int w = i % W;
    int h = (i / W) % H;
    int c = (i / (W * H)) % C;
    int b = i / (W * H * C);
    size_t ib = ((size_t)(b * C4 + 4 * c) * H + h) * W + w;
    size_t cs = (size_t)H * W;
    float v0 = in[ib];
    float v1 = 2.f * in[ib + cs]     - 1.f;
    float v2 = 2.f * in[ib + 2 * cs] - 1.f;
    float v3 = 2.f * in[ib + 3 * cs] - 1.f;
    float x00 = v0 + 0.5f * ( v1 + v2 + v3);
    float x01 = v0 + 0.5f * ( v1 - v2 - v3);
    float x10 = v0 + 0.5f * (-v1 + v2 - v3);
    float x11 = v0 + 0.5f * (-v1 - v2 + v3);
    int W2 = 2 * W;
    size_t ob = ((size_t)(b * Ctot + coff + c) * 2 * H + 2 * h) * W2 + 2 * w;
    out[ob]          = x00;
    out[ob + 1]      = x01;
    out[ob + W2]     = x10;
    out[ob + W2 + 1] = x11;
}

__global__ void copyskip_k(const float* __restrict__ src, float* __restrict__ dst,
                           int B, int Csrc, int Ctot, int HW) {
    int total = B * Csrc * HW;
    int i = blockIdx.x * blockDim.x + threadIdx.x;
    if (i >= total) return;
    int p = i % HW;
    int c = (i / HW) % Csrc;
    int b = i / (HW * Csrc);
    dst[((size_t)(b * Ctot) + c) * HW + p] = src[((size_t)(b * Csrc) + c) * HW + p];
}

// ---------------------------------------------------------------------------
// Direct 3x3 conv, pad=1. Inputs read straight from global (L1/L2 resident),
// weights double-buffered in smem via cp.async (duplicated to float2 for FFMA2).
// Thread: 2 rows x 4 cols output pixels x OCB output channels.
// Optional fused Haar DWT of the conv output into wtout.
// ---------------------------------------------------------------------------
template <int TCW, int TRH, int NIMG, int ICCHUNK, int OCB, bool RELU, bool ADD, bool FUSEWT>
__global__ void __launch_bounds__(TCW * TRH * NIMG)
conv3x3_k(const float* __restrict__ in, const float* __restrict__ wgt,
          const float* __restrict__ bias, const float* __restrict__ addsrc,
          float* __restrict__ out, float* __restrict__ wtout,
          int IC, int OC, int H, int W) {
    constexpr int NT = TCW * TRH * NIMG;
    constexpr int WN = ICCHUNK * OCB * 9;

    __shared__ float  s_raw[2][WN];
    __shared__ float2 s_dup[WN];

    const int tid  = threadIdx.x;
    const int tcol = tid % TCW;
    const int trow = (tid / TCW) % TRH;
    const int img  = tid / (TCW * TRH);
    const int tiles_h = H / (2 * TRH);
    const int tile_w  = blockIdx.x;
    const int tile_h  = blockIdx.y % tiles_h;
    const int bgrp    = blockIdx.y / tiles_h;
    const int b       = bgrp * NIMG + img;
    const int oc0     = blockIdx.z * OCB;
    const int h0 = tile_h * (2 * TRH) + 2 * trow;
    const int w0 = tile_w * (4 * TCW) + 4 * tcol;
    const size_t HWs = (size_t)H * W;

    const bool rv0 = (h0 > 0);
    const bool rv3 = (h0 + 2 < H);
    const bool lok = (w0 > 0);
    const bool rok = (w0 + 4 < W);

    ull acc[OCB][2][2];
#pragma unroll
    for (int o = 0; o < OCB; o++) {
        float bv = bias[oc0 + o];
        acc[o][0][0] = pk(bv, bv); acc[o][0][1] = pk(bv, bv);
        acc[o][1][0] = pk(bv, bv); acc[o][1][1] = pk(bv, bv);
    }

    const float* p = in + (size_t)b * IC * HWs + (size_t)(h0 - 1) * W + w0;

    const int nch = IC / ICCHUNK;

    // prologue prefetch (chunk 0)
    {
        for (int i = tid; i < WN; i += NT) {
            int o = i / (ICCHUNK * 9);
            int r = i - o * (ICCHUNK * 9);
            const float* src = wgt + ((size_t)(oc0 + o) * IC) * 9 + r;
            uint32_t dst = (uint32_t)__cvta_generic_to_shared(&s_raw[0][i]);
            asm volatile("cp.async.ca.shared.global [%0], [%1], 4;" :: "r"(dst), "l"(src));
        }
        asm volatile("cp.async.commit_group;" ::: "memory");
    }

    for (int c = 0; c < nch; c++) {
        asm volatile("cp.async.wait_group 0;" ::: "memory");
        __syncthreads();
        // duplicate raw weights into float2 lanes
        for (int i = tid; i < WN; i += NT) {
            float w = s_raw[c & 1][i];
            s_dup[i] = make_float2(w, w);
        }
        // prefetch next chunk
        if (c + 1 < nch) {
            const int ic0n = (c + 1) * ICCHUNK;
            for (int i = tid; i < WN; i += NT) {
                int o = i / (ICCHUNK * 9);
                int r = i - o * (ICCHUNK * 9);
                const float* src = wgt + ((size_t)(oc0 + o) * IC + ic0n) * 9 + r;
                uint32_t dst = (uint32_t)__cvta_generic_to_shared(&s_raw[(c + 1) & 1][i]);
                asm volatile("cp.async.ca.shared.global [%0], [%1], 4;" :: "r"(dst), "l"(src));
            }
        }
        asm volatile("cp.async.commit_group;" ::: "memory");
        __syncthreads();

#pragma unroll 2
        for (int kk = 0; kk < ICCHUNK; kk++) {
            ull rp[4][5];
#pragma unroll
            for (int r = 0; r < 4; r++) {
                bool vr = (r == 0) ? rv0 : (r == 3) ? rv3 : true;
                const float* q = p + r * W;
                float4 v = make_float4(0.f, 0.f, 0.f, 0.f);
                if (vr) v = *(const float4*)q;
                float cl = 0.f, cr = 0.f;
                if (vr && lok) cl = q[-1];
                if (vr && rok) cr = q[4];
                rp[r][0] = pk(cl,  v.x);
                rp[r][1] = pk(v.x, v.y);
                rp[r][2] = pk(v.y, v.z);
                rp[r][3] = pk(v.z, v.w);
                rp[r][4] = pk(v.w, cr);
            }
            p += HWs;
#pragma unroll
            for (int o = 0; o < OCB; o++) {
                const ull* wv = (const ull*)&s_dup[(o * ICCHUNK + kk) * 9];
#pragma unroll
                for (int ki = 0; ki < 3; ki++) {
                    ull wA = wv[ki * 3 + 0], wB = wv[ki * 3 + 1], wC = wv[ki * 3 + 2];
                    fma2(acc[o][0][0], rp[ki][0],     wA);
                    fma2(acc[o][0][0], rp[ki][1],     wB);
                    fma2(acc[o][0][0], rp[ki][2],     wC);
                    fma2(acc[o][0][1], rp[ki][2],     wA);
                    fma2(acc[o][0][1], rp[ki][3],     wB);
                    fma2(acc[o][0][1], rp[ki][4],     wC);
                    fma2(acc[o][1][0], rp[ki + 1][0], wA);
                    fma2(acc[o][1][0], rp[ki + 1][1], wB);
                    fma2(acc[o][1][0], rp[ki + 1][2], wC);
                    fma2(acc[o][1][1], rp[ki + 1][2], wA);
                    fma2(acc[o][1][1], rp[ki + 1][3], wB);
                    fma2(acc[o][1][1], rp[ki + 1][4], wC);
                }
            }
        }
    }

    // ---- epilogue: add / lrelu / store (+ optional fused DWT) ----
#pragma unroll
    for (int o = 0; o < OCB; o++) {
        float a0, a1, a2, a3, b0, b1, b2, b3;
        upk(a0, a1, acc[o][0][0]); upk(a2, a3, acc[o][0][1]);
        upk(b0, b1, acc[o][1][0]); upk(b2, b3, acc[o][1][1]);
        size_t base = ((size_t)(b * OC + oc0 + o) * H + h0) * W + w0;
        if (ADD) {
            float4 s0 = *(const float4*)&addsrc[base];
            float4 s1 = *(const float4*)&addsrc[base + W];
            a0 += s0.x; a1 += s0.y; a2 += s0.z; a3 += s0.w;
            b0 += s1.x; b1 += s1.y; b2 += s1.z; b3 += s1.w;
        }
        if (RELU) {
            a0 = (a0 >= 0.f) ? a0 : 0.2f * a0;  a1 = (a1 >= 0.f) ? a1 : 0.2f * a1;
            a2 = (a2 >= 0.f) ? a2 : 0.2f * a2;  a3 = (a3 >= 0.f) ? a3 : 0.2f * a3;
            b0 = (b0 >= 0.f) ? b0 : 0.2f * b0;  b1 = (b1 >= 0.f) ? b1 : 0.2f * b1;
            b2 = (b2 >= 0.f) ? b2 : 0.2f * b2;  b3 = (b3 >= 0.f) ? b3 : 0.2f * b3;
        }
        *(float4*)&out[base]     = make_float4(a0, a1, a2, a3);
        *(float4*)&out[base + W] = make_float4(b0, b1, b2, b3);

        if (FUSEWT) {
            // two 2x2 haar blocks: cols (0,1) and (2,3)
            float ll0 = 0.25f * (a0 + a1 + b0 + b1);
            float hl0 = 0.5f  * (a0 + a1 - b0 - b1);
            float lh0 = 0.5f  * (a0 - a1 + b0 - b1);
            float hh0 = 0.5f  * (a0 - a1 - b0 + b1);
            float ll1 = 0.25f * (a2 + a3 + b2 + b3);
            float hl1 = 0.5f  * (a2 + a3 - b2 - b3);
            float lh1 = 0.5f  * (a2 - a3 + b2 - b3);
            float hh1 = 0.5f  * (a2 - a3 - b2 + b3);
            hl0 = (hl0 + 1.f) * 0.5f; lh0 = (lh0 + 1.f) * 0.5f; hh0 = (hh0 + 1.f) * 0.5f;
            hl1 = (hl1 + 1.f) * 0.5f; lh1 = (lh1 + 1.f) * 0.5f; hh1 = (hh1 + 1.f) * 0.5f;
            const int Ho = H >> 1, Wo = W >> 1;
            size_t ch = (size_t)b * 4 * OC + 4 * (oc0 + o);
            size_t pos = (size_t)(h0 >> 1) * Wo + (w0 >> 1);
            size_t cs = (size_t)Ho * Wo;
            *(float2*)&wtout[ch * cs + pos]           = make_float2(ll0, ll1);
            *(float2*)&wtout[(ch + 1) * cs + pos]     = make_float2(hl0, hl1);
            *(float2*)&wtout[(ch + 2) * cs + pos]     = make_float2(lh0, lh1);
            *(float2*)&wtout[(ch + 3) * cs + pos]     = make_float2(hh0, hh1);
        }
    }
}

// ---------------------------------------------------------------------------
// Final: y = iwt(iw1[4,12,128,128]); out = 1x1 conv cfin @ y -> [4,3,256,256]
// ---------------------------------------------------------------------------
__global__ void final_k(const float* __restrict__ in, const float* __restrict__ cfin,
                        float* __restrict__ out, int B) {
    const int H = 128, W = 128;
    int total = B * H * W;
    int i = blockIdx.x * blockDim.x + threadIdx.x;
    if (i >= total) return;
    int w = i % W;
    int h = (i / W) % H;
    int b = i / (W * H);

    float y00[3], y01[3], y10[3], y11[3];
#pragma unroll
    for (int c = 0; c < 3; c++) {
        size_t ib = ((size_t)(b * 12 + 4 * c) * H + h) * W + w;
        size_t cs = (size_t)H * W;
        float v0 = in[ib];
        float v1 = 2.f * in[ib + cs]     - 1.f;
        float v2 = 2.f * in[ib + 2 * cs] - 1.f;
        float v3 = 2.f * in[ib + 3 * cs] - 1.f;
        y00[c] = v0 + 0.5f * ( v1 + v2 + v3);
        y01[c] = v0 + 0.5f * ( v1 - v2 - v3);
        y10[c] = v0 + 0.5f * (-v1 + v2 - v3);
        y11[c] = v0 + 0.5f * (-v1 - v2 + v3);
    }
    float m[9];
#pragma unroll
    for (int j = 0; j < 9; j++) m[j] = cfin[j];

    const int HO = 256, WO = 256;
#pragma unroll
    for (int o = 0; o < 3; o++) {
        float o00 = m[o*3+0]*y00[0] + m[o*3+1]*y00[1] + m[o*3+2]*y00[2];
        float o01 = m[o*3+0]*y01[0] + m[o*3+1]*y01[1] + m[o*3+2]*y01[2];
        float o10 = m[o*3+0]*y10[0] + m[o*3+1]*y10[1] + m[o*3+2]*y10[2];
        float o11 = m[o*3+0]*y11[0] + m[o*3+1]*y11[1] + m[o*3+2]*y11[2];
        size_t ob = ((size_t)(b * 3 + o) * HO + 2 * h) * WO + 2 * w;
        out[ob]          = o00;
        out[ob + 1]      = o01;
        out[ob + WO]     = o10;
        out[ob + WO + 1] = o11;
    }
}

// ---------------------------------------------------------------------------
// Host side
// ---------------------------------------------------------------------------
static inline int ceil_div(int a, int b) { return (a + b - 1) / b; }

extern "C" void kernel_launch(void* const* d_in, const int* in_sizes, int n_in,
                              void* d_out, int out_size) {
    (void)in_sizes; (void)n_in; (void)out_size;
    const float* x        = (const float*)d_in[0];
    const float* conv1_w  = (const float*)d_in[1];
    const float* conv1_b  = (const float*)d_in[2];
    const float* conv2_w  = (const float*)d_in[3];
    const float* conv2_b  = (const float*)d_in[4];
    const float* conv3_w  = (const float*)d_in[5];
    const float* conv3_b  = (const float*)d_in[6];
    const float* conv4_w  = (const float*)d_in[7];
    const float* conv4_b  = (const float*)d_in[8];
    const float* convd4_w = (const float*)d_in[9];
    const float* convd4_b = (const float*)d_in[10];
    const float* convd3_w = (const float*)d_in[11];
    const float* convd3_b = (const float*)d_in[12];
    const float* convd2_w = (const float*)d_in[13];
    const float* convd2_b = (const float*)d_in[14];
    const float* convd1_w = (const float*)d_in[15];
    const float* convd1_b = (const float*)d_in[16];
    const float* cfin_w   = (const float*)d_in[17];
    float* out = (float*)d_out;

    static float *p_w1=nullptr,*p_c1,*p_w2,*p_c2,*p_w3,*p_c3,*p_w4,*p_c4,*p_c5,
                 *p_ic4,*p_iw4,*p_ic3,*p_iw3,*p_ic2,*p_iw2,*p_ic1,*p_iw1;
    if (!p_w1) {
        cudaGetSymbolAddress((void**)&p_w1,  g_w1);
        cudaGetSymbolAddress((void**)&p_c1,  g_c1);
        cudaGetSymbolAddress((void**)&p_w2,  g_w2);
        cudaGetSymbolAddress((void**)&p_c2,  g_c2);
        cudaGetSymbolAddress((void**)&p_w3,  g_w3);
        cudaGetSymbolAddress((void**)&p_c3,  g_c3);
        cudaGetSymbolAddress((void**)&p_w4,  g_w4);
        cudaGetSymbolAddress((void**)&p_c4,  g_c4);
        cudaGetSymbolAddress((void**)&p_c5,  g_c5);
        cudaGetSymbolAddress((void**)&p_ic4, g_ic4);
        cudaGetSymbolAddress((void**)&p_iw4, g_iw4);
        cudaGetSymbolAddress((void**)&p_ic3, g_ic3);
        cudaGetSymbolAddress((void**)&p_iw3, g_iw3);
        cudaGetSymbolAddress((void**)&p_ic2, g_ic2);
        cudaGetSymbolAddress((void**)&p_iw2, g_iw2);
        cudaGetSymbolAddress((void**)&p_ic1, g_ic1);
        cudaGetSymbolAddress((void**)&p_iw1, g_iw1);
    }

    const int B = 4;

    // w1 = wt(x)
    wt_k<<<ceil_div(B*3*128*128, 256), 256>>>(x, p_w1, B, 3, 256, 256);

    // conv1: 12->16 @128x128, fused wt -> w2. 256thr, grid (2,16,8)=256
    conv3x3_k<16,16,1,12,2,true,false,true><<<dim3(2, 4*B, 8), 256>>>(
        p_w1, conv1_w, conv1_b, nullptr, p_c1, p_w2, 12, 16, 128, 128);

    // conv2: 64->64 @64x64, fused wt -> w3. 256thr, grid (1,8,32)=256
    conv3x3_k<16,16,1,16,2,true,false,true><<<dim3(1, 2*B, 32), 256>>>(
        p_w2, conv2_w, conv2_b, nullptr, p_c2, p_w3, 64, 64, 64, 64);

    // conv3: 256->256 @32x32, fused wt -> w4. 128thr, grid (1,4,128)=512
    conv3x3_k<8,16,1,16,2,true,false,true><<<dim3(1, 1*B, 128), 128>>>(
        p_w3, conv3_w, conv3_b, nullptr, p_c3, p_w4, 256, 256, 32, 32);

    // bottleneck: three conv4 1024->1024 @16x16. 128thr, grid (1,1,512)=512
    conv3x3_k<4,8,4,16,2,true,false,false><<<dim3(1, 1, 512), 128>>>(
        p_w4, conv4_w, conv4_b, nullptr, p_c4, nullptr, 1024, 1024, 16, 16);
    conv3x3_k<4,8,4,16,2,true,false,false><<<dim3(1, 1, 512), 128>>>(
        p_c4, conv4_w, conv4_b, nullptr, p_c5, nullptr, 1024, 1024, 16, 16);
    conv3x3_k<4,8,4,16,2,true,true,false><<<dim3(1, 1, 512), 128>>>(
        p_c5, conv4_w, conv4_b, p_w4, p_ic4, nullptr, 1024, 1024, 16, 16);

    // decoder
    iwt_k<<<ceil_div(B*256*16*16, 256), 256>>>(p_ic4, p_iw4, B, 1024, 16, 16, 512, 256);
    copyskip_k<<<ceil_div(B*256*32*32, 256), 256>>>(p_c3, p_iw4, B, 256, 512, 32*32);

    // convd4: 512->256 @32x32. 128thr, grid (1,4,128)=512
    conv3x3_k<8,16,1,16,2,true,false,false><<<dim3(1, 1*B, 128), 128>>>(
        p_iw4, convd4_w, convd4_b, nullptr, p_ic3, nullptr, 512, 256, 32, 32);

    iwt_k<<<ceil_div(B*64*32*32, 256), 256>>>(p_ic3, p_iw3, B, 256, 32, 32, 128, 64);
    copyskip_k<<<ceil_div(B*64*64*64, 256), 256>>>(p_c2, p_iw3, B, 64, 128, 64*64);

    // convd3: 128->64 @64x64. 256thr, grid (1,8,32)=256
    conv3x3_k<16,16,1,16,2,true,false,false><<<dim3(1, 2*B, 32), 256>>>(
        p_iw3, convd3_w, convd3_b, nullptr, p_ic2, nullptr, 128, 64, 64, 64);

    iwt_k<<<ceil_div(B*16*64*64, 256), 256>>>(p_ic2, p_iw2, B, 64, 64, 64, 32, 16);
    copyskip_k<<<ceil_div(B*16*128*128, 256), 256>>>(p_c1, p_iw2, B, 16, 32, 128*128);

    // convd2: 32->16 @128x128. 256thr, grid (2,16,8)=256
    conv3x3_k<16,16,1,16,2,true,false,false><<<dim3(2, 4*B, 8), 256>>>(
        p_iw2, convd2_w, convd2_b, nullptr, p_ic1, nullptr, 32, 16, 128, 128);

    // convd1: 16->12 @128x128. 256thr, grid (2,16,6)=192
    conv3x3_k<16,16,1,16,2,true,false,false><<<dim3(2, 4*B, 6), 256>>>(
        p_ic1, convd1_w, convd1_b, nullptr, p_iw1, nullptr, 16, 12, 128, 128);

    // fused final iwt + 1x1
    final_k<<<ceil_div(B*128*128, 256), 256>>>(p_iw1, cfin_w, out, B);
}

// round 5
// speedup vs baseline: 2.9034x; 1.3569x over previous
#include <cuda_runtime.h>
#include <cstdint>

typedef unsigned long long ull;

// ---------------------------------------------------------------------------
// Scratch buffers (device globals; no allocation allowed)
// ---------------------------------------------------------------------------
__device__ float g_w1 [786432];    // [4,12,128,128]
__device__ float g_c1 [1048576];   // [4,16,128,128]
__device__ float g_w2 [1048576];   // [4,64,64,64]
__device__ float g_c2 [1048576];   // [4,64,64,64]
__device__ float g_w3 [1048576];   // [4,256,32,32]
__device__ float g_c3 [1048576];   // [4,256,32,32]
__device__ float g_w4 [1048576];   // [4,1024,16,16]
__device__ float g_c4 [1048576];
__device__ float g_c5 [1048576];
__device__ float g_ic4[1048576];
__device__ float g_iw4[2097152];   // [4,512,32,32]
__device__ float g_ic3[1048576];   // [4,256,32,32]
__device__ float g_iw3[2097152];   // [4,128,64,64]
__device__ float g_ic2[1048576];   // [4,64,64,64]
__device__ float g_iw2[2097152];   // [4,32,128,128]
__device__ float g_ic1[1048576];   // [4,16,128,128]
__device__ float g_iw1[786432];    // [4,12,128,128]

// ---------------------------------------------------------------------------
// f32x2 packed helpers (Blackwell FFMA2)
// ---------------------------------------------------------------------------
__device__ __forceinline__ ull pk(float x, float y) {
    ull r;
    asm("mov.b64 %0, {%1, %2};" : "=l"(r) : "f"(x), "f"(y));
    return r;
}
__device__ __forceinline__ void upk(float& x, float& y, ull v) {
    asm("mov.b64 {%0, %1}, %2;" : "=f"(x), "=f"(y) : "l"(v));
}
__device__ __forceinline__ void fma2(ull& d, ull a, ull b) {
    asm("fma.rn.f32x2 %0, %1, %2, %0;" : "+l"(d) : "l"(a), "l"(b));
}

// ---------------------------------------------------------------------------
// Haar DWT (standalone, only for the network input x)
// ---------------------------------------------------------------------------
__global__ void wt_k(const float* __restrict__ in, float* __restrict__ out,
                     int B, int C, int H, int W) {
    int Ho = H >> 1, Wo = W >> 1;
    int total = B * C * Ho * Wo;
    int i = blockIdx.x * blockDim.x + threadIdx.x;
    if (i >= total) return;
    int w = i % Wo;
    int h = (i / Wo) % Ho;
    int c = (i / (Wo * Ho)) % C;
    int b = i / (Wo * Ho * C);
    const float* p = in + ((size_t)(b * C + c) * H + 2 * h) * W + 2 * w;
    float a  = p[0], bb = p[1], cc = p[W], d = p[W + 1];
    float ll = 0.25f * (a + bb + cc + d);
    float hl = 0.5f  * (a + bb - cc - d);
    float lh = 0.5f  * (a - bb + cc - d);
    float hh = 0.5f  * (a - bb - cc + d);
    size_t ob = ((size_t)(b * 4 * C + 4 * c) * Ho + h) * Wo + w;
    size_t cs = (size_t)Ho * Wo;
    out[ob]          = ll;
    out[ob + cs]     = (hl + 1.f) * 0.5f;
    out[ob + 2 * cs] = (lh + 1.f) * 0.5f;
    out[ob + 3 * cs] = (hh + 1.f) * 0.5f;
}

// ---------------------------------------------------------------------------
// Haar IWT into concat buffer at channel offset
// ---------------------------------------------------------------------------
__global__ void iwt_k(const float* __restrict__ in, float* __restrict__ out,
                      int B, int C4, int H, int W, int Ctot, int coff) {
    int C = C4 >> 2;
    int total = B * C * H * W;
    int i = blockIdx.x * blockDim.x + threadIdx.x;
    if (i >= total) return;
    int w = i % W;
    int h = (i / W) % H;
    int c = (i / (W * H)) % C;
    int b = i / (W * H * C);
    size_t ib = ((size_t)(b * C4 + 4 * c) * H + h) * W + w;
    size_t cs = (size_t)H * W;
    float v0 = in[ib];
    float v1 = 2.f * in[ib + cs]     - 1.f;
    float v2 = 2.f * in[ib + 2 * cs] - 1.f;
    float v3 = 2.f * in[ib + 3 * cs] - 1.f;
    float x00 = v0 + 0.5f * ( v1 + v2 + v3);
    float x01 = v0 + 0.5f * ( v1 - v2 - v3);
    float x10 = v0 + 0.5f * (-v1 + v2 - v3);
    float x11 = v0 + 0.5f * (-v1 - v2 + v3);
    int W2 = 2 * W;
    size_t ob = ((size_t)(b * Ctot + coff + c) * 2 * H + 2 * h) * W2 + 2 * w;
    out[ob]          = x00;
    out[ob + 1]      = x01;
    out[ob + W2]     = x10;
    out[ob + W2 + 1] = x11;
}

__global__ void copyskip_k(const float* __restrict__ src, float* __restrict__ dst,
                           int B, int Csrc, int Ctot, int HW) {
    int total = B * Csrc * HW;
    int i = blockIdx.x * blockDim.x + threadIdx.x;
    if (i >= total) return;
    int p = i % HW;
    int c = (i / HW) % Csrc;
    int b = i / (HW * Csrc);
    dst[((size_t)(b * Ctot) + c) * HW + p] = src[((size_t)(b * Csrc) + c) * HW + p];
}

// ---------------------------------------------------------------------------
// Direct 3x3 conv, pad=1 — oc-pair lane packing.
// f32x2 lanes hold TWO OUTPUT CHANNELS; inputs are broadcast pairs.
// Thread: 2x2 pixels x NP oc-pairs (2*NP channels).
// Weights cp.async double-buffered, pre-packed as (w_ocA, w_ocB) float2.
// ---------------------------------------------------------------------------
template <int H, int W, int TPX, int TOC, int NP, int ICCHUNK,
          bool RELU, bool ADD, bool FUSEWT>
__global__ void __launch_bounds__(TPX * TOC)
convp_k(const float* __restrict__ in, const float* __restrict__ wgt,
        const float* __restrict__ bias, const float* __restrict__ addsrc,
        float* __restrict__ out, float* __restrict__ wtout, int IC, int OC) {
    constexpr int NT    = TPX * TOC;
    constexpr int OCBLK = TOC * 2 * NP;
    constexpr int PAIRS = OCBLK / 2;
    constexpr int WN    = OCBLK * ICCHUNK * 9;   // raw weight floats / chunk
    constexpr int DN    = ICCHUNK * 9 * PAIRS;   // packed float2 count
    constexpr int TILESIMG = (H / 2) * (W / 2);

    __shared__ float  s_raw[2][WN];
    __shared__ float2 s_dup[DN];

    const int tid = threadIdx.x;
    const int tpx = tid % TPX;
    const int toc = tid / TPX;
    const int g   = blockIdx.x * TPX + tpx;
    const int img = g / TILESIMG;
    const int rem = g % TILESIMG;
    const int h0  = (rem / (W / 2)) * 2;
    const int w0  = (rem % (W / 2)) * 2;
    const int oc0 = blockIdx.y * OCBLK;
    const int pairbase = toc * NP;

    const size_t HW = (size_t)H * W;
    const bool vr0 = (h0 > 0);
    const bool vr3 = (h0 + 2 < H);
    const bool lok = (w0 > 0);
    const bool rok = (w0 + 2 < W);

    ull acc[NP][2][2];
#pragma unroll
    for (int np = 0; np < NP; np++) {
        int P = oc0 + 2 * (pairbase + np);
        float bA = bias[P], bB = bias[P + 1];
#pragma unroll
        for (int r = 0; r < 2; r++)
#pragma unroll
            for (int c = 0; c < 2; c++) acc[np][r][c] = pk(bA, bB);
    }

    // base pointer at (row h0-1, col w0-1)
    const float* p0 = in + (size_t)img * IC * HW + (size_t)(h0 - 1) * W + (w0 - 1);
    const int nch = IC / ICCHUNK;

    // prologue: prefetch weight chunk 0
    for (int i = tid; i < WN; i += NT) {
        int o = i / (ICCHUNK * 9);
        int r = i - o * (ICCHUNK * 9);
        const float* src = wgt + ((size_t)(oc0 + o) * IC) * 9 + r;
        uint32_t dst = (uint32_t)__cvta_generic_to_shared(&s_raw[0][i]);
        asm volatile("cp.async.ca.shared.global [%0], [%1], 4;" :: "r"(dst), "l"(src));
    }
    asm volatile("cp.async.commit_group;" ::: "memory");

    float cl[2][4], cx[2][4], cy[2][4], cr[2][4];

    for (int ch = 0; ch < nch; ch++) {
        asm volatile("cp.async.wait_group 0;" ::: "memory");
        __syncthreads();
        // pack weights into oc-pair float2
        for (int i = tid; i < DN; i += NT) {
            int pr = i % PAIRS;
            int t  = i / PAIRS;
            s_dup[i] = make_float2(s_raw[ch & 1][(2 * pr) * (ICCHUNK * 9) + t],
                                   s_raw[ch & 1][(2 * pr + 1) * (ICCHUNK * 9) + t]);
        }
        if (ch + 1 < nch) {
            const int ic0n = (ch + 1) * ICCHUNK;
            for (int i = tid; i < WN; i += NT) {
                int o = i / (ICCHUNK * 9);
                int r = i - o * (ICCHUNK * 9);
                const float* src = wgt + ((size_t)(oc0 + o) * IC + ic0n) * 9 + r;
                uint32_t dst = (uint32_t)__cvta_generic_to_shared(&s_raw[(ch + 1) & 1][i]);
                asm volatile("cp.async.ca.shared.global [%0], [%1], 4;" :: "r"(dst), "l"(src));
            }
        }
        asm volatile("cp.async.commit_group;" ::: "memory");
        __syncthreads();

        const float* pb = p0 + (size_t)(ch * ICCHUNK) * HW;
        // load ic 0 of chunk into buffer 0
#pragma unroll
        for (int ri = 0; ri < 4; ri++) {
            bool vr = (ri == 0) ? vr0 : (ri == 3) ? vr3 : true;
            const float* q = pb + ri * W;
            float2 m = make_float2(0.f, 0.f);
            float l = 0.f, r = 0.f;
            if (vr) {
                m = *(const float2*)(q + 1);
                if (lok) l = q[0];
                if (rok) r = q[3];
            }
            cl[0][ri] = l; cx[0][ri] = m.x; cy[0][ri] = m.y; cr[0][ri] = r;
        }

#pragma unroll 2
        for (int kk = 0; kk < ICCHUNK; kk++) {
            const int cb = kk & 1;
            // prefetch next ic
            if (kk + 1 < ICCHUNK) {
                const float* pn = pb + (size_t)(kk + 1) * HW;
#pragma unroll
                for (int ri = 0; ri < 4; ri++) {
                    bool vr = (ri == 0) ? vr0 : (ri == 3) ? vr3 : true;
                    const float* q = pn + ri * W;
                    float2 m = make_float2(0.f, 0.f);
                    float l = 0.f, r = 0.f;
                    if (vr) {
                        m = *(const float2*)(q + 1);
                        if (lok) l = q[0];
                        if (rok) r = q[3];
                    }
                    cl[cb ^ 1][ri] = l; cx[cb ^ 1][ri] = m.x;
                    cy[cb ^ 1][ri] = m.y; cr[cb ^ 1][ri] = r;
                }
            }
            // broadcast-pack current ic
            ull bp[4][4];
#pragma unroll
            for (int ri = 0; ri < 4; ri++) {
                bp[ri][0] = pk(cl[cb][ri], cl[cb][ri]);
                bp[ri][1] = pk(cx[cb][ri], cx[cb][ri]);
                bp[ri][2] = pk(cy[cb][ri], cy[cb][ri]);
                bp[ri][3] = pk(cr[cb][ri], cr[cb][ri]);
            }
            const float2* wrow = s_dup + (size_t)kk * 9 * PAIRS + pairbase;
#pragma unroll
            for (int np = 0; np < NP; np++) {
#pragma unroll
                for (int ki = 0; ki < 3; ki++)
#pragma unroll
                    for (int kj = 0; kj < 3; kj++) {
                        ull wp = *(const ull*)&wrow[(ki * 3 + kj) * PAIRS + np];
                        fma2(acc[np][0][0], bp[ki][kj],         wp);
                        fma2(acc[np][0][1], bp[ki][kj + 1],     wp);
                        fma2(acc[np][1][0], bp[ki + 1][kj],     wp);
                        fma2(acc[np][1][1], bp[ki + 1][kj + 1], wp);
                    }
            }
        }
    }

    // ---- epilogue ----
#pragma unroll
    for (int np = 0; np < NP; np++) {
        float a00, b00, a01, b01, a10, b10, a11, b11;
        upk(a00, b00, acc[np][0][0]); upk(a01, b01, acc[np][0][1]);
        upk(a10, b10, acc[np][1][0]); upk(a11, b11, acc[np][1][1]);
        const int ocA = oc0 + 2 * (pairbase + np);
#pragma unroll
        for (int s = 0; s < 2; s++) {
            float v00 = s ? b00 : a00, v01 = s ? b01 : a01;
            float v10 = s ? b10 : a10, v11 = s ? b11 : a11;
            const int oc = ocA + s;
            size_t base = ((size_t)(img * OC + oc) * H + h0) * W + w0;
            if (ADD) {
                float2 s0 = *(const float2*)&addsrc[base];
                float2 s1 = *(const float2*)&addsrc[base + W];
                v00 += s0.x; v01 += s0.y; v10 += s1.x; v11 += s1.y;
            }
            if (RELU) {
                v00 = (v00 >= 0.f) ? v00 : 0.2f * v00;
                v01 = (v01 >= 0.f) ? v01 : 0.2f * v01;
                v10 = (v10 >= 0.f) ? v10 : 0.2f * v10;
                v11 = (v11 >= 0.f) ? v11 : 0.2f * v11;
            }
            *(float2*)&out[base]     = make_float2(v00, v01);
            *(float2*)&out[base + W] = make_float2(v10, v11);
            if (FUSEWT) {
                float ll = 0.25f * (v00 + v01 + v10 + v11);
                float hl = 0.5f  * (v00 + v01 - v10 - v11);
                float lh = 0.5f  * (v00 - v01 + v10 - v11);
                float hh = 0.5f  * (v00 - v01 - v10 + v11);
                hl = (hl + 1.f) * 0.5f; lh = (lh + 1.f) * 0.5f; hh = (hh + 1.f) * 0.5f;
                const size_t cs = HW / 4;
                size_t ob = ((size_t)img * 4 * OC + 4 * oc) * cs
                          + (size_t)(h0 >> 1) * (W >> 1) + (w0 >> 1);
                wtout[ob]          = ll;
                wtout[ob + cs]     = hl;
                wtout[ob + 2 * cs] = lh;
                wtout[ob + 3 * cs] = hh;
            }
        }
    }
}

// ---------------------------------------------------------------------------
// Final: y = iwt(iw1[4,12,128,128]); out = 1x1 conv cfin @ y -> [4,3,256,256]
// ---------------------------------------------------------------------------
__global__ void final_k(const float* __restrict__ in, const float* __restrict__ cfin,
                        float* __restrict__ out, int B) {
    const int H = 128, W = 128;
    int total = B * H * W;
    int i = blockIdx.x * blockDim.x + threadIdx.x;
    if (i >= total) return;
    int w = i % W;
    int h = (i / W) % H;
    int b = i / (W * H);

    float y00[3], y01[3], y10[3], y11[3];
#pragma unroll
    for (int c = 0; c < 3; c++) {
        size_t ib = ((size_t)(b * 12 + 4 * c) * H + h) * W + w;
        size_t cs = (size_t)H * W;
        float v0 = in[ib];
        float v1 = 2.f * in[ib + cs]     - 1.f;
        float v2 = 2.f * in[ib + 2 * cs] - 1.f;
        float v3 = 2.f * in[ib + 3 * cs] - 1.f;
        y00[c] = v0 + 0.5f * ( v1 + v2 + v3);
        y01[c] = v0 + 0.5f * ( v1 - v2 - v3);
        y10[c] = v0 + 0.5f * (-v1 + v2 - v3);
        y11[c] = v0 + 0.5f * (-v1 - v2 + v3);
    }
    float m[9];
#pragma unroll
    for (int j = 0; j < 9; j++) m[j] = cfin[j];

    const int HO = 256, WO = 256;
#pragma unroll
    for (int o = 0; o < 3; o++) {
        float o00 = m[o*3+0]*y00[0] + m[o*3+1]*y00[1] + m[o*3+2]*y00[2];
        float o01 = m[o*3+0]*y01[0] + m[o*3+1]*y01[1] + m[o*3+2]*y01[2];
        float o10 = m[o*3+0]*y10[0] + m[o*3+1]*y10[1] + m[o*3+2]*y10[2];
        float o11 = m[o*3+0]*y11[0] + m[o*3+1]*y11[1] + m[o*3+2]*y11[2];
        size_t ob = ((size_t)(b * 3 + o) * HO + 2 * h) * WO + 2 * w;
        out[ob]          = o00;
        out[ob + 1]      = o01;
        out[ob + WO]     = o10;
        out[ob + WO + 1] = o11;
    }
}

// ---------------------------------------------------------------------------
// Host side
// ---------------------------------------------------------------------------
static inline int ceil_div(int a, int b) { return (a + b - 1) / b; }

extern "C" void kernel_launch(void* const* d_in, const int* in_sizes, int n_in,
                              void* d_out, int out_size) {
    (void)in_sizes; (void)n_in; (void)out_size;
    const float* x        = (const float*)d_in[0];
    const float* conv1_w  = (const float*)d_in[1];
    const float* conv1_b  = (const float*)d_in[2];
    const float* conv2_w  = (const float*)d_in[3];
    const float* conv2_b  = (const float*)d_in[4];
    const float* conv3_w  = (const float*)d_in[5];
    const float* conv3_b  = (const float*)d_in[6];
    const float* conv4_w  = (const float*)d_in[7];
    const float* conv4_b  = (const float*)d_in[8];
    const float* convd4_w = (const float*)d_in[9];
    const float* convd4_b = (const float*)d_in[10];
    const float* convd3_w = (const float*)d_in[11];
    const float* convd3_b = (const float*)d_in[12];
    const float* convd2_w = (const float*)d_in[13];
    const float* convd2_b = (const float*)d_in[14];
    const float* convd1_w = (const float*)d_in[15];
    const float* convd1_b = (const float*)d_in[16];
    const float* cfin_w   = (const float*)d_in[17];
    float* out = (float*)d_out;

    static float *p_w1=nullptr,*p_c1,*p_w2,*p_c2,*p_w3,*p_c3,*p_w4,*p_c4,*p_c5,
                 *p_ic4,*p_iw4,*p_ic3,*p_iw3,*p_ic2,*p_iw2,*p_ic1,*p_iw1;
    if (!p_w1) {
        cudaGetSymbolAddress((void**)&p_w1,  g_w1);
        cudaGetSymbolAddress((void**)&p_c1,  g_c1);
        cudaGetSymbolAddress((void**)&p_w2,  g_w2);
        cudaGetSymbolAddress((void**)&p_c2,  g_c2);
        cudaGetSymbolAddress((void**)&p_w3,  g_w3);
        cudaGetSymbolAddress((void**)&p_c3,  g_c3);
        cudaGetSymbolAddress((void**)&p_w4,  g_w4);
        cudaGetSymbolAddress((void**)&p_c4,  g_c4);
        cudaGetSymbolAddress((void**)&p_c5,  g_c5);
        cudaGetSymbolAddress((void**)&p_ic4, g_ic4);
        cudaGetSymbolAddress((void**)&p_iw4, g_iw4);
        cudaGetSymbolAddress((void**)&p_ic3, g_ic3);
        cudaGetSymbolAddress((void**)&p_iw3, g_iw3);
        cudaGetSymbolAddress((void**)&p_ic2, g_ic2);
        cudaGetSymbolAddress((void**)&p_iw2, g_iw2);
        cudaGetSymbolAddress((void**)&p_ic1, g_ic1);
        cudaGetSymbolAddress((void**)&p_iw1, g_iw1);
    }

    // w1 = wt(x)
    wt_k<<<ceil_div(4*3*128*128, 256), 256>>>(x, p_w1, 4, 3, 256, 256);

    // conv1: 12->16 @128², fused wt -> w2.  grid (256,2) x128
    convp_k<128,128,64,2,2,12,true,false,true><<<dim3(256, 2), 128>>>(
        p_w1, conv1_w, conv1_b, nullptr, p_c1, p_w2, 12, 16);

    // conv2: 64->64 @64², fused wt -> w3.  grid (64,8) x128
    convp_k<64,64,64,2,2,16,true,false,true><<<dim3(64, 8), 128>>>(
        p_w2, conv2_w, conv2_b, nullptr, p_c2, p_w3, 64, 64);

    // conv3: 256->256 @32², fused wt -> w4.  grid (16,32) x128
    convp_k<32,32,64,2,2,16,true,false,true><<<dim3(16, 32), 128>>>(
        p_w3, conv3_w, conv3_b, nullptr, p_c3, p_w4, 256, 256);

    // bottleneck: three conv4 1024->1024 @16².  grid (4,128) x128
    convp_k<16,16,64,2,2,16,true,false,false><<<dim3(4, 128), 128>>>(
        p_w4, conv4_w, conv4_b, nullptr, p_c4, nullptr, 1024, 1024);
    convp_k<16,16,64,2,2,16,true,false,false><<<dim3(4, 128), 128>>>(
        p_c4, conv4_w, conv4_b, nullptr, p_c5, nullptr, 1024, 1024);
    convp_k<16,16,64,2,2,16,true,true,false><<<dim3(4, 128), 128>>>(
        p_c5, conv4_w, conv4_b, p_w4, p_ic4, nullptr, 1024, 1024);

    // decoder
    iwt_k<<<ceil_div(4*256*16*16, 256), 256>>>(p_ic4, p_iw4, 4, 1024, 16, 16, 512, 256);
    copyskip_k<<<ceil_div(4*256*32*32, 256), 256>>>(p_c3, p_iw4, 4, 256, 512, 32*32);

    // convd4: 512->256 @32².  grid (16,32) x128
    convp_k<32,32,64,2,2,16,true,false,false><<<dim3(16, 32), 128>>>(
        p_iw4, convd4_w, convd4_b, nullptr, p_ic3, nullptr, 512, 256);

    iwt_k<<<ceil_div(4*64*32*32, 256), 256>>>(p_ic3, p_iw3, 4, 256, 32, 32, 128, 64);
    copyskip_k<<<ceil_div(4*64*64*64, 256), 256>>>(p_c2, p_iw3, 4, 64, 128, 64*64);

    // convd3: 128->64 @64².  grid (64,8) x128
    convp_k<64,64,64,2,2,16,true,false,false><<<dim3(64, 8), 128>>>(
        p_iw3, convd3_w, convd3_b, nullptr, p_ic2, nullptr, 128, 64);

    iwt_k<<<ceil_div(4*16*64*64, 256), 256>>>(p_ic2, p_iw2, 4, 64, 64, 64, 32, 16);
    copyskip_k<<<ceil_div(4*16*128*128, 256), 256>>>(p_c1, p_iw2, 4, 16, 32, 128*128);

    // convd2: 32->16 @128².  grid (256,2) x128
    convp_k<128,128,64,2,2,16,true,false,false><<<dim3(256, 2), 128>>>(
        p_iw2, convd2_w, convd2_b, nullptr, p_ic1, nullptr, 32, 16);

    // convd1: 16->12 @128².  NP=3 -> OCBLK=12. grid (256,1) x128
    convp_k<128,128,64,2,3,16,true,false,false><<<dim3(256, 1), 128>>>(
        p_ic1, convd1_w, convd1_b, nullptr, p_iw1, nullptr, 16, 12);

    // fused final iwt + 1x1
    final_k<<<ceil_div(4*128*128, 256), 256>>>(p_iw1, cfin_w, out, 4);
}

// round 6
// speedup vs baseline: 3.0380x; 1.0464x over previous
#include <cuda_runtime.h>
#include <cstdint>

typedef unsigned long long ull;

// ---------------------------------------------------------------------------
// Scratch buffers (device globals; no allocation allowed)
// ---------------------------------------------------------------------------
__device__ float g_w1 [786432];    // [4,12,128,128]
__device__ float g_c1 [1048576];   // [4,16,128,128]
__device__ float g_w2 [1048576];   // [4,64,64,64]
__device__ float g_c2 [1048576];   // [4,64,64,64]
__device__ float g_w3 [1048576];   // [4,256,32,32]
__device__ float g_c3 [1048576];   // [4,256,32,32]
__device__ float g_w4 [1048576];   // [4,1024,16,16]
__device__ float g_c4 [1048576];
__device__ float g_c5 [1048576];
__device__ float g_ic4[1048576];
__device__ float g_iw4[2097152];   // [4,512,32,32]
__device__ float g_ic3[1048576];   // [4,256,32,32]
__device__ float g_iw3[2097152];   // [4,128,64,64]
__device__ float g_ic2[1048576];   // [4,64,64,64]
__device__ float g_iw2[2097152];   // [4,32,128,128]
__device__ float g_ic1[1048576];   // [4,16,128,128]
__device__ float g_iw1[786432];    // [4,12,128,128]

// ---------------------------------------------------------------------------
// f32x2 packed helpers (Blackwell FFMA2)
// ---------------------------------------------------------------------------
__device__ __forceinline__ ull pk(float x, float y) {
    ull r;
    asm("mov.b64 %0, {%1, %2};" : "=l"(r) : "f"(x), "f"(y));
    return r;
}
__device__ __forceinline__ void upk(float& x, float& y, ull v) {
    asm("mov.b64 {%0, %1}, %2;" : "=f"(x), "=f"(y) : "l"(v));
}
__device__ __forceinline__ void fma2(ull& d, ull a, ull b) {
    asm("fma.rn.f32x2 %0, %1, %2, %0;" : "+l"(d) : "l"(a), "l"(b));
}

// ---------------------------------------------------------------------------
// Haar DWT (standalone, only for the network input x)
// ---------------------------------------------------------------------------
__global__ void wt_k(const float* __restrict__ in, float* __restrict__ out,
                     int B, int C, int H, int W) {
    int Ho = H >> 1, Wo = W >> 1;
    int total = B * C * Ho * Wo;
    int i = blockIdx.x * blockDim.x + threadIdx.x;
    if (i >= total) return;
    int w = i % Wo;
    int h = (i / Wo) % Ho;
    int c = (i / (Wo * Ho)) % C;
    int b = i / (Wo * Ho * C);
    const float* p = in + ((size_t)(b * C + c) * H + 2 * h) * W + 2 * w;
    float a  = p[0], bb = p[1], cc = p[W], d = p[W + 1];
    float ll = 0.25f * (a + bb + cc + d);
    float hl = 0.5f  * (a + bb - cc - d);
    float lh = 0.5f  * (a - bb + cc - d);
    float hh = 0.5f  * (a - bb - cc + d);
    size_t ob = ((size_t)(b * 4 * C + 4 * c) * Ho + h) * Wo + w;
    size_t cs = (size_t)Ho * Wo;
    out[ob]          = ll;
    out[ob + cs]     = (hl + 1.f) * 0.5f;
    out[ob + 2 * cs] = (lh + 1.f) * 0.5f;
    out[ob + 3 * cs] = (hh + 1.f) * 0.5f;
}

// ---------------------------------------------------------------------------
// Haar IWT into concat buffer at channel offset
// ---------------------------------------------------------------------------
__global__ void iwt_k(const float* __restrict__ in, float* __restrict__ out,
                      int B, int C4, int H, int W, int Ctot, int coff) {
    int C = C4 >> 2;
    int total = B * C * H * W;
    int i = blockIdx.x * blockDim.x + threadIdx.x;
    if (i >= total) return;
    int w = i % W;
    int h = (i / W) % H;
    int c = (i / (W * H)) % C;
    int b = i / (W * H * C);
    size_t ib = ((size_t)(b * C4 + 4 * c) * H + h) * W + w;
    size_t cs = (size_t)H * W;
    float v0 = in[ib];
    float v1 = 2.f * in[ib + cs]     - 1.f;
    float v2 = 2.f * in[ib + 2 * cs] - 1.f;
    float v3 = 2.f * in[ib + 3 * cs] - 1.f;
    float x00 = v0 + 0.5f * ( v1 + v2 + v3);
    float x01 = v0 + 0.5f * ( v1 - v2 - v3);
    float x10 = v0 + 0.5f * (-v1 + v2 - v3);
    float x11 = v0 + 0.5f * (-v1 - v2 + v3);
    int W2 = 2 * W;
    size_t ob = ((size_t)(b * Ctot + coff + c) * 2 * H + 2 * h) * W2 + 2 * w;
    out[ob]          = x00;
    out[ob + 1]      = x01;
    out[ob + W2]     = x10;
    out[ob + W2 + 1] = x11;
}

__global__ void copyskip_k(const float* __restrict__ src, float* __restrict__ dst,
                           int B, int Csrc, int Ctot, int HW) {
    int total = B * Csrc * HW;
    int i = blockIdx.x * blockDim.x + threadIdx.x;
    if (i >= total) return;
    int p = i % HW;
    int c = (i / HW) % Csrc;
    int b = i / (HW * Csrc);
    dst[((size_t)(b * Ctot) + c) * HW + p] = src[((size_t)(b * Csrc) + c) * HW + p];
}

// ---------------------------------------------------------------------------
// Direct 3x3 conv, pad=1 — oc-pair lane packing, NP pairs (2*NP ocs)/thread.
// f32x2 lanes hold TWO OUTPUT CHANNELS; inputs are broadcast pairs.
// Thread: 2x2 pixels x NP oc-pairs. Weights cp.async double-buffered,
// pre-packed as (w_ocA, w_ocB) float2 in smem.
// ---------------------------------------------------------------------------
template <int H, int W, int TPX, int TOC, int NP, int ICCHUNK,
          bool RELU, bool ADD, bool FUSEWT>
__global__ void __launch_bounds__(TPX * TOC)
convp_k(const float* __restrict__ in, const float* __restrict__ wgt,
        const float* __restrict__ bias, const float* __restrict__ addsrc,
        float* __restrict__ out, float* __restrict__ wtout, int IC, int OC) {
    constexpr int NT    = TPX * TOC;
    constexpr int OCBLK = TOC * 2 * NP;
    constexpr int PAIRS = OCBLK / 2;
    constexpr int WN    = OCBLK * ICCHUNK * 9;   // raw weight floats / chunk
    constexpr int DN    = ICCHUNK * 9 * PAIRS;   // packed float2 count
    constexpr int TILESIMG = (H / 2) * (W / 2);

    __shared__ float  s_raw[2][WN];
    __shared__ float2 s_dup[DN];

    const int tid = threadIdx.x;
    const int tpx = tid % TPX;
    const int toc = tid / TPX;
    const int g   = blockIdx.x * TPX + tpx;
    const int img = g / TILESIMG;
    const int rem = g % TILESIMG;
    const int h0  = (rem / (W / 2)) * 2;
    const int w0  = (rem % (W / 2)) * 2;
    const int oc0 = blockIdx.y * OCBLK;
    const int pairbase = toc * NP;

    const size_t HW = (size_t)H * W;
    const bool vr0 = (h0 > 0);
    const bool vr3 = (h0 + 2 < H);
    const bool lok = (w0 > 0);
    const bool rok = (w0 + 2 < W);

    ull acc[NP][2][2];
#pragma unroll
    for (int np = 0; np < NP; np++) {
        int P = oc0 + 2 * (pairbase + np);
        float bA = bias[P], bB = bias[P + 1];
#pragma unroll
        for (int r = 0; r < 2; r++)
#pragma unroll
            for (int c = 0; c < 2; c++) acc[np][r][c] = pk(bA, bB);
    }

    // base pointer at (row h0-1, col w0-1)
    const float* p0 = in + (size_t)img * IC * HW + (size_t)(h0 - 1) * W + (w0 - 1);
    const int nch = IC / ICCHUNK;

    // prologue: prefetch weight chunk 0
    for (int i = tid; i < WN; i += NT) {
        int o = i / (ICCHUNK * 9);
        int r = i - o * (ICCHUNK * 9);
        const float* src = wgt + ((size_t)(oc0 + o) * IC) * 9 + r;
        uint32_t dst = (uint32_t)__cvta_generic_to_shared(&s_raw[0][i]);
        asm volatile("cp.async.ca.shared.global [%0], [%1], 4;" :: "r"(dst), "l"(src));
    }
    asm volatile("cp.async.commit_group;" ::: "memory");

    float cl[2][4], cx[2][4], cy[2][4], cr[2][4];

    for (int ch = 0; ch < nch; ch++) {
        asm volatile("cp.async.wait_group 0;" ::: "memory");
        __syncthreads();
        // pack weights into oc-pair float2
        for (int i = tid; i < DN; i += NT) {
            int pr = i % PAIRS;
            int t  = i / PAIRS;
            s_dup[i] = make_float2(s_raw[ch & 1][(2 * pr) * (ICCHUNK * 9) + t],
                                   s_raw[ch & 1][(2 * pr + 1) * (ICCHUNK * 9) + t]);
        }
        if (ch + 1 < nch) {
            const int ic0n = (ch + 1) * ICCHUNK;
            for (int i = tid; i < WN; i += NT) {
                int o = i / (ICCHUNK * 9);
                int r = i - o * (ICCHUNK * 9);
                const float* src = wgt + ((size_t)(oc0 + o) * IC + ic0n) * 9 + r;
                uint32_t dst = (uint32_t)__cvta_generic_to_shared(&s_raw[(ch + 1) & 1][i]);
                asm volatile("cp.async.ca.shared.global [%0], [%1], 4;" :: "r"(dst), "l"(src));
            }
        }
        asm volatile("cp.async.commit_group;" ::: "memory");
        __syncthreads();

        const float* pb = p0 + (size_t)(ch * ICCHUNK) * HW;
        // load ic 0 of chunk into buffer 0
#pragma unroll
        for (int ri = 0; ri < 4; ri++) {
            bool vr = (ri == 0) ? vr0 : (ri == 3) ? vr3 : true;
            const float* q = pb + ri * W;
            float2 m = make_float2(0.f, 0.f);
            float l = 0.f, r = 0.f;
            if (vr) {
                m = *(const float2*)(q + 1);
                if (lok) l = q[0];
                if (rok) r = q[3];
            }
            cl[0][ri] = l; cx[0][ri] = m.x; cy[0][ri] = m.y; cr[0][ri] = r;
        }

#pragma unroll 2
        for (int kk = 0; kk < ICCHUNK; kk++) {
            const int cb = kk & 1;
            // prefetch next ic
            if (kk + 1 < ICCHUNK) {
                const float* pn = pb + (size_t)(kk + 1) * HW;
#pragma unroll
                for (int ri = 0; ri < 4; ri++) {
                    bool vr = (ri == 0) ? vr0 : (ri == 3) ? vr3 : true;
                    const float* q = pn + ri * W;
                    float2 m = make_float2(0.f, 0.f);
                    float l = 0.f, r = 0.f;
                    if (vr) {
                        m = *(const float2*)(q + 1);
                        if (lok) l = q[0];
                        if (rok) r = q[3];
                    }
                    cl[cb ^ 1][ri] = l; cx[cb ^ 1][ri] = m.x;
                    cy[cb ^ 1][ri] = m.y; cr[cb ^ 1][ri] = r;
                }
            }
            // broadcast-pack current ic
            ull bp[4][4];
#pragma unroll
            for (int ri = 0; ri < 4; ri++) {
                bp[ri][0] = pk(cl[cb][ri], cl[cb][ri]);
                bp[ri][1] = pk(cx[cb][ri], cx[cb][ri]);
                bp[ri][2] = pk(cy[cb][ri], cy[cb][ri]);
                bp[ri][3] = pk(cr[cb][ri], cr[cb][ri]);
            }
            const float2* wrow = s_dup + (size_t)kk * 9 * PAIRS + pairbase;
#pragma unroll
            for (int np = 0; np < NP; np++) {
#pragma unroll
                for (int ki = 0; ki < 3; ki++)
#pragma unroll
                    for (int kj = 0; kj < 3; kj++) {
                        ull wp = *(const ull*)&wrow[(ki * 3 + kj) * PAIRS + np];
                        fma2(acc[np][0][0], bp[ki][kj],         wp);
                        fma2(acc[np][0][1], bp[ki][kj + 1],     wp);
                        fma2(acc[np][1][0], bp[ki + 1][kj],     wp);
                        fma2(acc[np][1][1], bp[ki + 1][kj + 1], wp);
                    }
            }
        }
    }

    // ---- epilogue ----
#pragma unroll
    for (int np = 0; np < NP; np++) {
        float a00, b00, a01, b01, a10, b10, a11, b11;
        upk(a00, b00, acc[np][0][0]); upk(a01, b01, acc[np][0][1]);
        upk(a10, b10, acc[np][1][0]); upk(a11, b11, acc[np][1][1]);
        const int ocA = oc0 + 2 * (pairbase + np);
#pragma unroll
        for (int s = 0; s < 2; s++) {
            float v00 = s ? b00 : a00, v01 = s ? b01 : a01;
            float v10 = s ? b10 : a10, v11 = s ? b11 : a11;
            const int oc = ocA + s;
            size_t base = ((size_t)(img * OC + oc) * H + h0) * W + w0;
            if (ADD) {
                float2 s0 = *(const float2*)&addsrc[base];
                float2 s1 = *(const float2*)&addsrc[base + W];
                v00 += s0.x; v01 += s0.y; v10 += s1.x; v11 += s1.y;
            }
            if (RELU) {
                v00 = (v00 >= 0.f) ? v00 : 0.2f * v00;
                v01 = (v01 >= 0.f) ? v01 : 0.2f * v01;
                v10 = (v10 >= 0.f) ? v10 : 0.2f * v10;
                v11 = (v11 >= 0.f) ? v11 : 0.2f * v11;
            }
            *(float2*)&out[base]     = make_float2(v00, v01);
            *(float2*)&out[base + W] = make_float2(v10, v11);
            if (FUSEWT) {
                float ll = 0.25f * (v00 + v01 + v10 + v11);
                float hl = 0.5f  * (v00 + v01 - v10 - v11);
                float lh = 0.5f  * (v00 - v01 + v10 - v11);
                float hh = 0.5f  * (v00 - v01 - v10 + v11);
                hl = (hl + 1.f) * 0.5f; lh = (lh + 1.f) * 0.5f; hh = (hh + 1.f) * 0.5f;
                const size_t cs = HW / 4;
                size_t ob = ((size_t)img * 4 * OC + 4 * oc) * cs
                          + (size_t)(h0 >> 1) * (W >> 1) + (w0 >> 1);
                wtout[ob]          = ll;
                wtout[ob + cs]     = hl;
                wtout[ob + 2 * cs] = lh;
                wtout[ob + 3 * cs] = hh;
            }
        }
    }
}

// ---------------------------------------------------------------------------
// Final: y = iwt(iw1[4,12,128,128]); out = 1x1 conv cfin @ y -> [4,3,256,256]
// ---------------------------------------------------------------------------
__global__ void final_k(const float* __restrict__ in, const float* __restrict__ cfin,
                        float* __restrict__ out, int B) {
    const int H = 128, W = 128;
    int total = B * H * W;
    int i = blockIdx.x * blockDim.x + threadIdx.x;
    if (i >= total) return;
    int w = i % W;
    int h = (i / W) % H;
    int b = i / (W * H);

    float y00[3], y01[3], y10[3], y11[3];
#pragma unroll
    for (int c = 0; c < 3; c++) {
        size_t ib = ((size_t)(b * 12 + 4 * c) * H + h) * W + w;
        size_t cs = (size_t)H * W;
        float v0 = in[ib];
        float v1 = 2.f * in[ib + cs]     - 1.f;
        float v2 = 2.f * in[ib + 2 * cs] - 1.f;
        float v3 = 2.f * in[ib + 3 * cs] - 1.f;
        y00[c] = v0 + 0.5f * ( v1 + v2 + v3);
        y01[c] = v0 + 0.5f * ( v1 - v2 - v3);
        y10[c] = v0 + 0.5f * (-v1 + v2 - v3);
        y11[c] = v0 + 0.5f * (-v1 - v2 + v3);
    }
    float m[9];
#pragma unroll
    for (int j = 0; j < 9; j++) m[j] = cfin[j];

    const int HO = 256, WO = 256;
#pragma unroll
    for (int o = 0; o < 3; o++) {
        float o00 = m[o*3+0]*y00[0] + m[o*3+1]*y00[1] + m[o*3+2]*y00[2];
        float o01 = m[o*3+0]*y01[0] + m[o*3+1]*y01[1] + m[o*3+2]*y01[2];
        float o10 = m[o*3+0]*y10[0] + m[o*3+1]*y10[1] + m[o*3+2]*y10[2];
        float o11 = m[o*3+0]*y11[0] + m[o*3+1]*y11[1] + m[o*3+2]*y11[2];
        size_t ob = ((size_t)(b * 3 + o) * HO + 2 * h) * WO + 2 * w;
        out[ob]          = o00;
        out[ob + 1]      = o01;
        out[ob + WO]     = o10;
        out[ob + WO + 1] = o11;
    }
}

// ---------------------------------------------------------------------------
// Host side
// ---------------------------------------------------------------------------
static inline int ceil_div(int a, int b) { return (a + b - 1) / b; }

extern "C" void kernel_launch(void* const* d_in, const int* in_sizes, int n_in,
                              void* d_out, int out_size) {
    (void)in_sizes; (void)n_in; (void)out_size;
    const float* x        = (const float*)d_in[0];
    const float* conv1_w  = (const float*)d_in[1];
    const float* conv1_b  = (const float*)d_in[2];
    const float* conv2_w  = (const float*)d_in[3];
    const float* conv2_b  = (const float*)d_in[4];
    const float* conv3_w  = (const float*)d_in[5];
    const float* conv3_b  = (const float*)d_in[6];
    const float* conv4_w  = (const float*)d_in[7];
    const float* conv4_b  = (const float*)d_in[8];
    const float* convd4_w = (const float*)d_in[9];
    const float* convd4_b = (const float*)d_in[10];
    const float* convd3_w = (const float*)d_in[11];
    const float* convd3_b = (const float*)d_in[12];
    const float* convd2_w = (const float*)d_in[13];
    const float* convd2_b = (const float*)d_in[14];
    const float* convd1_w = (const float*)d_in[15];
    const float* convd1_b = (const float*)d_in[16];
    const float* cfin_w   = (const float*)d_in[17];
    float* out = (float*)d_out;

    static float *p_w1=nullptr,*p_c1,*p_w2,*p_c2,*p_w3,*p_c3,*p_w4,*p_c4,*p_c5,
                 *p_ic4,*p_iw4,*p_ic3,*p_iw3,*p_ic2,*p_iw2,*p_ic1,*p_iw1;
    if (!p_w1) {
        cudaGetSymbolAddress((void**)&p_w1,  g_w1);
        cudaGetSymbolAddress((void**)&p_c1,  g_c1);
        cudaGetSymbolAddress((void**)&p_w2,  g_w2);
        cudaGetSymbolAddress((void**)&p_c2,  g_c2);
        cudaGetSymbolAddress((void**)&p_w3,  g_w3);
        cudaGetSymbolAddress((void**)&p_c3,  g_c3);
        cudaGetSymbolAddress((void**)&p_w4,  g_w4);
        cudaGetSymbolAddress((void**)&p_c4,  g_c4);
        cudaGetSymbolAddress((void**)&p_c5,  g_c5);
        cudaGetSymbolAddress((void**)&p_ic4, g_ic4);
        cudaGetSymbolAddress((void**)&p_iw4, g_iw4);
        cudaGetSymbolAddress((void**)&p_ic3, g_ic3);
        cudaGetSymbolAddress((void**)&p_iw3, g_iw3);
        cudaGetSymbolAddress((void**)&p_ic2, g_ic2);
        cudaGetSymbolAddress((void**)&p_iw2, g_iw2);
        cudaGetSymbolAddress((void**)&p_ic1, g_ic1);
        cudaGetSymbolAddress((void**)&p_iw1, g_iw1);
    }

    // w1 = wt(x)
    wt_k<<<ceil_div(4*3*128*128, 256), 256>>>(x, p_w1, 4, 3, 256, 256);

    // conv1: 12->16 @128², NP=4 (OCBLK=16), fused wt -> w2.  grid (256,1) x128
    convp_k<128,128,64,2,4,12,true,false,true><<<dim3(256, 1), 128>>>(
        p_w1, conv1_w, conv1_b, nullptr, p_c1, p_w2, 12, 16);

    // conv2: 64->64 @64², NP=4, fused wt -> w3.  grid (64,4) x128
    convp_k<64,64,64,2,4,16,true,false,true><<<dim3(64, 4), 128>>>(
        p_w2, conv2_w, conv2_b, nullptr, p_c2, p_w3, 64, 64);

    // conv3: 256->256 @32², NP=4, fused wt -> w4.  grid (16,16) x128
    convp_k<32,32,64,2,4,16,true,false,true><<<dim3(16, 16), 128>>>(
        p_w3, conv3_w, conv3_b, nullptr, p_c3, p_w4, 256, 256);

    // bottleneck: three conv4 1024->1024 @16², NP=4.  grid (4,64) x128
    convp_k<16,16,64,2,4,16,true,false,false><<<dim3(4, 64), 128>>>(
        p_w4, conv4_w, conv4_b, nullptr, p_c4, nullptr, 1024, 1024);
    convp_k<16,16,64,2,4,16,true,false,false><<<dim3(4, 64), 128>>>(
        p_c4, conv4_w, conv4_b, nullptr, p_c5, nullptr, 1024, 1024);
    convp_k<16,16,64,2,4,16,true,true,false><<<dim3(4, 64), 128>>>(
        p_c5, conv4_w, conv4_b, p_w4, p_ic4, nullptr, 1024, 1024);

    // decoder
    iwt_k<<<ceil_div(4*256*16*16, 256), 256>>>(p_ic4, p_iw4, 4, 1024, 16, 16, 512, 256);
    copyskip_k<<<ceil_div(4*256*32*32, 256), 256>>>(p_c3, p_iw4, 4, 256, 512, 32*32);

    // convd4: 512->256 @32², NP=4.  grid (16,16) x128
    convp_k<32,32,64,2,4,16,true,false,false><<<dim3(16, 16), 128>>>(
        p_iw4, convd4_w, convd4_b, nullptr, p_ic3, nullptr, 512, 256);

    iwt_k<<<ceil_div(4*64*32*32, 256), 256>>>(p_ic3, p_iw3, 4, 256, 32, 32, 128, 64);
    copyskip_k<<<ceil_div(4*64*64*64, 256), 256>>>(p_c2, p_iw3, 4, 64, 128, 64*64);

    // convd3: 128->64 @64², NP=4.  grid (64,4) x128
    convp_k<64,64,64,2,4,16,true,false,false><<<dim3(64, 4), 128>>>(
        p_iw3, convd3_w, convd3_b, nullptr, p_ic2, nullptr, 128, 64);

    iwt_k<<<ceil_div(4*16*64*64, 256), 256>>>(p_ic2, p_iw2, 4, 64, 64, 64, 32, 16);
    copyskip_k<<<ceil_div(4*16*128*128, 256), 256>>>(p_c1, p_iw2, 4, 16, 32, 128*128);

    // convd2: 32->16 @128², NP=4 (OCBLK=16).  grid (256,1) x128
    convp_k<128,128,64,2,4,16,true,false,false><<<dim3(256, 1), 128>>>(
        p_iw2, convd2_w, convd2_b, nullptr, p_ic1, nullptr, 32, 16);

    // convd1: 16->12 @128², NP=3 (OCBLK=12).  grid (256,1) x128
    convp_k<128,128,64,2,3,16,true,false,false><<<dim3(256, 1), 128>>>(
        p_ic1, convd1_w, convd1_b, nullptr, p_iw1, nullptr, 16, 12);

    // fused final iwt + 1x1
    final_k<<<ceil_div(4*128*128, 256), 256>>>(p_iw1, cfin_w, out, 4);
}